// round 2
// baseline (speedup 1.0000x reference)
#include <cuda_runtime.h>
#include <math_constants.h>

#define N_NODES 100000
#define N_EDGES 200000
#define NG      2000
#define H       32

// ---------------- device scratch (alloc-free) ----------------
__device__ float g_h[N_NODES * H];                 // node hidden     12.8 MB
__device__ float g_m[N_NODES * H];                 // aggregated msgs 12.8 MB
__device__ float g_r[N_EDGES * 64];                // edge hidden     51.2 MB
__device__ float g_A[(long long)N_EDGES * 1024];   // edge matrices  819.2 MB
__device__ float g_sh[NG * H];                     // set2set h
__device__ float g_sc[NG * H];                     // set2set c
__device__ float g_rr[NG * H];                     // readout r
__device__ int   g_offs[NG + 1];                   // graph segment offsets

// ---------------- helpers ----------------
__device__ __forceinline__ unsigned long long pk2(float x) {
    unsigned long long r;
    asm("mov.b64 %0, {%1, %1};" : "=l"(r) : "f"(x));
    return r;
}
__device__ __forceinline__ unsigned long long fma2(unsigned long long a,
                                                   unsigned long long b,
                                                   unsigned long long c) {
    unsigned long long d;
    asm("fma.rn.f32x2 %0, %1, %2, %3;" : "=l"(d) : "l"(a), "l"(b), "l"(c));
    return d;
}
__device__ __forceinline__ void unpk2(unsigned long long v, float& lo, float& hi) {
    asm("mov.b64 {%0, %1}, %2;" : "=f"(lo), "=f"(hi) : "l"(v));
}
__device__ __forceinline__ float warpMax(float v) {
    #pragma unroll
    for (int o = 16; o > 0; o >>= 1) v = fmaxf(v, __shfl_xor_sync(0xffffffffu, v, o));
    return v;
}
__device__ __forceinline__ float warpSum(float v) {
    #pragma unroll
    for (int o = 16; o > 0; o >>= 1) v += __shfl_xor_sync(0xffffffffu, v, o);
    return v;
}
__device__ __forceinline__ float sigm(float x) { return 1.0f / (1.0f + expf(-x)); }

// ---------------- zero kernels ----------------
__global__ void k_zero_m() {
    int i = blockIdx.x * blockDim.x + threadIdx.x;
    if (i < N_NODES * H) g_m[i] = 0.0f;
}
__global__ void k_zero_s2s() {
    int i = blockIdx.x * blockDim.x + threadIdx.x;
    if (i < NG * H) { g_sh[i] = 0.0f; g_sc[i] = 0.0f; g_rr[i] = 0.0f; }
}

// ---------------- encoder: h = nf @ enc_W + enc_b ----------------
__global__ void k_encode(const float* __restrict__ nf, const float* __restrict__ W,
                         const float* __restrict__ b) {
    __shared__ float sW[16 * 32];
    __shared__ float sb[32];
    int t = threadIdx.x;
    for (int i = t; i < 512; i += 256) sW[i] = W[i];   // FIX: strided (blockDim=256)
    if (t < 32) sb[t] = b[t];
    __syncthreads();
    int n = blockIdx.x * blockDim.x + t;
    if (n >= N_NODES) return;
    float x[16];
    const float4* p = (const float4*)(nf + (long long)n * 16);
    #pragma unroll
    for (int q = 0; q < 4; q++) {
        float4 v = p[q];
        x[q*4+0] = v.x; x[q*4+1] = v.y; x[q*4+2] = v.z; x[q*4+3] = v.w;
    }
    #pragma unroll
    for (int c = 0; c < 32; c++) {
        float acc = sb[c];
        #pragma unroll
        for (int d = 0; d < 16; d++) acc += x[d] * sW[d * 32 + c];
        g_h[n * 32 + c] = acc;
    }
}

// ---------------- edge hidden: r = relu(ef @ e_W1 + e_b1) ----------------
__global__ void k_edgehid(const float* __restrict__ ef, const float* __restrict__ W,
                          const float* __restrict__ b) {
    __shared__ float sW[8 * 64];
    __shared__ float sb[64];
    int t = threadIdx.x;
    for (int i = t; i < 512; i += 256) sW[i] = W[i];   // FIX: strided (blockDim=256)
    if (t < 64) sb[t] = b[t];
    __syncthreads();
    int e = blockIdx.x * blockDim.x + t;
    if (e >= N_EDGES) return;
    float x[8];
    const float4* p = (const float4*)(ef + (long long)e * 8);
    float4 v0 = p[0], v1 = p[1];
    x[0]=v0.x; x[1]=v0.y; x[2]=v0.z; x[3]=v0.w;
    x[4]=v1.x; x[5]=v1.y; x[6]=v1.z; x[7]=v1.w;
    #pragma unroll
    for (int c = 0; c < 64; c++) {
        float acc = sb[c];
        #pragma unroll
        for (int d = 0; d < 8; d++) acc += x[d] * sW[d * 64 + c];
        g_r[(long long)e * 64 + c] = fmaxf(acc, 0.0f);
    }
}

// ---------------- A GEMM: A[E,1024] = r[E,64] @ W2[64,1024] + b2 ----------------
// BM=64, BN=256, BK=32 (2 k-tiles). 256 thr: tm=t>>6 (4), tn=t&63 (64).
// Thread outputs: rows tm*16 + [0,16), cols tn + 64*j, j<4. Accumulators are
// f32x2 pairs over adjacent rows (M-paired -> natural LDS.128 a-frags, 4 packs/k).
#define GBM 64
#define GBN 256
#define GBK 32
__global__ void __launch_bounds__(256) k_gemmA(const float* __restrict__ W2,
                                               const float* __restrict__ b2) {
    __shared__ float Rs[GBK][GBM];   // [k][m]  8 KB
    __shared__ float Ws[GBK][GBN];   // [k][n] 32 KB
    int t  = threadIdx.x;
    int e0 = blockIdx.y * GBM;
    int n0 = blockIdx.x * GBN;
    int tm = t >> 6;
    int tn = t & 63;
    int tm16 = tm * 16;

    unsigned long long acc[8][4];
    #pragma unroll
    for (int j = 0; j < 4; j++) {
        unsigned long long bd = pk2(__ldg(&b2[n0 + tn + 64 * j]));
        #pragma unroll
        for (int mi = 0; mi < 8; mi++) acc[mi][j] = bd;
    }

    #pragma unroll
    for (int kt = 0; kt < 2; kt++) {
        int k0 = kt * GBK;
        // load R tile (transposed into [k][m])
        #pragma unroll
        for (int i = 0; i < 2; i++) {
            int idx = t + 256 * i;          // 512 float4
            int m   = idx >> 3;
            int kq  = idx & 7;
            float4 v = *(const float4*)&g_r[(long long)(e0 + m) * 64 + k0 + kq * 4];
            Rs[kq*4+0][m] = v.x; Rs[kq*4+1][m] = v.y;
            Rs[kq*4+2][m] = v.z; Rs[kq*4+3][m] = v.w;
        }
        // load W tile
        #pragma unroll
        for (int i = 0; i < 8; i++) {
            int idx = t + 256 * i;          // 2048 float4
            int k   = idx >> 6;
            int nq  = idx & 63;
            *(float4*)&Ws[k][nq * 4] =
                *(const float4*)&W2[(long long)(k0 + k) * 1024 + n0 + nq * 4];
        }
        __syncthreads();

        #pragma unroll
        for (int k = 0; k < GBK; k++) {
            unsigned long long av[8];
            const ulonglong2* ap = (const ulonglong2*)&Rs[k][tm16];
            ulonglong2 a0 = ap[0], a1 = ap[1], a2 = ap[2], a3 = ap[3];
            av[0]=a0.x; av[1]=a0.y; av[2]=a1.x; av[3]=a1.y;
            av[4]=a2.x; av[5]=a2.y; av[6]=a3.x; av[7]=a3.y;
            #pragma unroll
            for (int j = 0; j < 4; j++) {
                unsigned long long bd = pk2(Ws[k][tn + 64 * j]);
                #pragma unroll
                for (int mi = 0; mi < 8; mi++) acc[mi][j] = fma2(av[mi], bd, acc[mi][j]);
            }
        }
        __syncthreads();
    }

    // epilogue
    #pragma unroll
    for (int mi = 0; mi < 8; mi++) {
        int row = e0 + tm16 + 2 * mi;
        #pragma unroll
        for (int j = 0; j < 4; j++) {
            float lo, hi;
            unpk2(acc[mi][j], lo, hi);
            int col = n0 + tn + 64 * j;
            g_A[(long long)row * 1024 + col]       = lo;
            g_A[(long long)(row + 1) * 1024 + col] = hi;
        }
    }
}

// ---------------- message pass: m[tgt] += A[e] @ h[src] ----------------
// one warp per edge; lane i computes msg[i] = sum_j A[e, i*32+j] * h[src, j]
__global__ void __launch_bounds__(256) k_message(const int* __restrict__ ei) {
    int lane = threadIdx.x & 31;
    int e = (blockIdx.x * blockDim.x + threadIdx.x) >> 5;
    if (e >= N_EDGES) return;
    int src = ei[e];
    int tgt = ei[N_EDGES + e];
    float hv = g_h[src * 32 + lane];
    const float4* Ar = (const float4*)&g_A[(long long)e * 1024 + lane * 32];
    float acc = 0.0f;
    #pragma unroll
    for (int u = 0; u < 8; u++) {
        float4 a4 = Ar[u];
        acc += a4.x * __shfl_sync(0xffffffffu, hv, 4*u+0);
        acc += a4.y * __shfl_sync(0xffffffffu, hv, 4*u+1);
        acc += a4.z * __shfl_sync(0xffffffffu, hv, 4*u+2);
        acc += a4.w * __shfl_sync(0xffffffffu, hv, 4*u+3);
    }
    atomicAdd(&g_m[tgt * 32 + lane], acc);
}

// ---------------- GRU cell: h = GRU(m, h) ----------------
__global__ void __launch_bounds__(256) k_gru(const float* __restrict__ Wih,
                                             const float* __restrict__ Whh,
                                             const float* __restrict__ bih,
                                             const float* __restrict__ bhh) {
    __shared__ float sWi[96 * 32];
    __shared__ float sWh[96 * 32];
    __shared__ float sbi[96];
    __shared__ float sbh[96];
    int t = threadIdx.x;
    for (int i = t; i < 96 * 32; i += 256) { sWi[i] = Wih[i]; sWh[i] = Whh[i]; }
    if (t < 96) { sbi[t] = bih[t]; sbh[t] = bhh[t]; }
    __syncthreads();
    int n = blockIdx.x * blockDim.x + t;
    if (n >= N_NODES) return;

    float mv[32], hv[32];
    const float4* mp = (const float4*)&g_m[n * 32];
    const float4* hp = (const float4*)&g_h[n * 32];
    #pragma unroll
    for (int q = 0; q < 8; q++) {
        float4 a = mp[q]; mv[q*4]=a.x; mv[q*4+1]=a.y; mv[q*4+2]=a.z; mv[q*4+3]=a.w;
        float4 b = hp[q]; hv[q*4]=b.x; hv[q*4+1]=b.y; hv[q*4+2]=b.z; hv[q*4+3]=b.w;
    }
    float hn[32];
    #pragma unroll 4
    for (int k = 0; k < 32; k++) {
        float gir = sbi[k],      ghr = sbh[k];
        float giz = sbi[32 + k], ghz = sbh[32 + k];
        float gin = sbi[64 + k], ghn = sbh[64 + k];
        #pragma unroll
        for (int c = 0; c < 32; c++) {
            float m_ = mv[c], h_ = hv[c];
            gir += m_ * sWi[k * 32 + c];        ghr += h_ * sWh[k * 32 + c];
            giz += m_ * sWi[(32 + k) * 32 + c]; ghz += h_ * sWh[(32 + k) * 32 + c];
            gin += m_ * sWi[(64 + k) * 32 + c]; ghn += h_ * sWh[(64 + k) * 32 + c];
        }
        float r = sigm(gir + ghr);
        float z = sigm(giz + ghz);
        float nn = tanhf(gin + r * ghn);
        hn[k] = (1.0f - z) * nn + z * hv[k];
    }
    float4* outp = (float4*)&g_h[n * 32];
    #pragma unroll
    for (int q = 0; q < 8; q++)
        outp[q] = make_float4(hn[q*4], hn[q*4+1], hn[q*4+2], hn[q*4+3]);
}

// ---------------- graph segment offsets (batch_indices sorted) ----------------
__global__ void k_offs(const int* __restrict__ batch) {
    int n = blockIdx.x * blockDim.x + threadIdx.x;
    if (n >= N_NODES) return;
    int b = batch[n];
    int prev = (n == 0) ? -1 : batch[n - 1];
    for (int g = prev + 1; g <= b; g++) g_offs[g] = n;
    if (n == N_NODES - 1)
        for (int g = b + 1; g <= NG; g++) g_offs[g] = N_NODES;
}

// ---------------- Set2Set attention + readout (online softmax, warp/graph) ----
__global__ void __launch_bounds__(256) k_attend() {
    int lane = threadIdx.x & 31;
    int g = (blockIdx.x * blockDim.x + threadIdx.x) >> 5;
    if (g >= NG) return;
    int s = g_offs[g], tEnd = g_offs[g + 1];
    float q = g_sh[g * 32 + lane];
    float maxv = -CUDART_INF_F, denom = 0.0f, racc = 0.0f;

    for (int base = s; base < tEnd; base += 32) {
        int n = base + lane;
        bool act = n < tEnd;
        int nn = act ? n : base;
        const float* hp = &g_h[nn * 32];
        float ev = 0.0f;
        #pragma unroll
        for (int j = 0; j < 32; j++) {
            float qj = __shfl_sync(0xffffffffu, q, j);
            ev += hp[j] * qj;
        }
        float e_n = act ? ev : -CUDART_INF_F;
        float cm = warpMax(e_n);
        float nm = fmaxf(maxv, cm);
        float scale = (maxv == -CUDART_INF_F) ? 0.0f : expf(maxv - nm);
        float p = act ? expf(e_n - nm) : 0.0f;
        float ps = warpSum(p);
        denom = denom * scale + ps;
        racc *= scale;
        maxv = nm;
        int cnt = min(32, tEnd - base);
        for (int n2 = 0; n2 < cnt; n2++) {
            float pn = __shfl_sync(0xffffffffu, p, n2);
            racc += pn * g_h[(base + n2) * 32 + lane];
        }
    }
    g_rr[g * 32 + lane] = (denom > 0.0f) ? (racc / denom) : 0.0f;
}

// ---------------- Set2Set LSTM step (thread per graph) ----------------
__global__ void k_lstm(const float* __restrict__ Wih, const float* __restrict__ Whh,
                       const float* __restrict__ bih, const float* __restrict__ bhh) {
    int g = blockIdx.x * blockDim.x + threadIdx.x;
    if (g >= NG) return;
    float hv[32], rv[32], cv[32];
    #pragma unroll
    for (int c = 0; c < 32; c++) {
        hv[c] = g_sh[g * 32 + c];
        rv[c] = g_rr[g * 32 + c];
        cv[c] = g_sc[g * 32 + c];
    }
    float hnew[32], cnew[32];
    for (int k = 0; k < 32; k++) {
        float gi = __ldg(&bih[k])      + __ldg(&bhh[k]);
        float gf = __ldg(&bih[32 + k]) + __ldg(&bhh[32 + k]);
        float gg = __ldg(&bih[64 + k]) + __ldg(&bhh[64 + k]);
        float go = __ldg(&bih[96 + k]) + __ldg(&bhh[96 + k]);
        #pragma unroll
        for (int c = 0; c < 32; c++) {
            float h_ = hv[c], r_ = rv[c];
            gi += h_ * __ldg(&Wih[k * 64 + c])        + r_ * __ldg(&Wih[k * 64 + 32 + c])
                + h_ * __ldg(&Whh[k * 32 + c]);
            gf += h_ * __ldg(&Wih[(32 + k) * 64 + c]) + r_ * __ldg(&Wih[(32 + k) * 64 + 32 + c])
                + h_ * __ldg(&Whh[(32 + k) * 32 + c]);
            gg += h_ * __ldg(&Wih[(64 + k) * 64 + c]) + r_ * __ldg(&Wih[(64 + k) * 64 + 32 + c])
                + h_ * __ldg(&Whh[(64 + k) * 32 + c]);
            go += h_ * __ldg(&Wih[(96 + k) * 64 + c]) + r_ * __ldg(&Wih[(96 + k) * 64 + 32 + c])
                + h_ * __ldg(&Whh[(96 + k) * 32 + c]);
        }
        float i_ = sigm(gi), f_ = sigm(gf), o_ = sigm(go), g_ = tanhf(gg);
        float cn = f_ * cv[k] + i_ * g_;
        cnew[k] = cn;
        hnew[k] = o_ * tanhf(cn);
    }
    #pragma unroll
    for (int c = 0; c < 32; c++) {
        g_sc[g * 32 + c] = cnew[c];
        g_sh[g * 32 + c] = hnew[c];
    }
}

// ---------------- output head ----------------
__global__ void k_output(const float* __restrict__ W1, const float* __restrict__ b1,
                         const float* __restrict__ W2, const float* __restrict__ b2,
                         float* __restrict__ out) {
    int g = blockIdx.x * blockDim.x + threadIdx.x;
    if (g >= NG) return;
    float emb[64];
    #pragma unroll
    for (int c = 0; c < 32; c++) {
        emb[c]      = g_sh[g * 32 + c];
        emb[32 + c] = g_rr[g * 32 + c];
    }
    float hid[32];
    #pragma unroll
    for (int c = 0; c < 32; c++) {
        float acc = __ldg(&b1[c]);
        #pragma unroll
        for (int d = 0; d < 64; d++) acc += emb[d] * __ldg(&W1[d * 32 + c]);
        hid[c] = fmaxf(acc, 0.0f);
    }
    #pragma unroll
    for (int k = 0; k < 3; k++) {
        float acc = __ldg(&b2[k]);
        #pragma unroll
        for (int c = 0; c < 32; c++) acc += hid[c] * __ldg(&W2[c * 3 + k]);
        out[g * 3 + k] = acc;
    }
}

// ---------------- launch ----------------
extern "C" void kernel_launch(void* const* d_in, const int* in_sizes, int n_in,
                              void* d_out, int out_size) {
    const float* nf     = (const float*)d_in[0];
    const float* ef     = (const float*)d_in[1];
    const float* enc_W  = (const float*)d_in[2];
    const float* enc_b  = (const float*)d_in[3];
    const float* e_W1   = (const float*)d_in[4];
    const float* e_b1   = (const float*)d_in[5];
    const float* e_W2   = (const float*)d_in[6];
    const float* e_b2   = (const float*)d_in[7];
    const float* gWih   = (const float*)d_in[8];
    const float* gWhh   = (const float*)d_in[9];
    const float* gbih   = (const float*)d_in[10];
    const float* gbhh   = (const float*)d_in[11];
    const float* lWih   = (const float*)d_in[12];
    const float* lWhh   = (const float*)d_in[13];
    const float* lbih   = (const float*)d_in[14];
    const float* lbhh   = (const float*)d_in[15];
    const float* oW1    = (const float*)d_in[16];
    const float* ob1    = (const float*)d_in[17];
    const float* oW2    = (const float*)d_in[18];
    const float* ob2    = (const float*)d_in[19];
    const int*   eidx   = (const int*)d_in[20];
    const int*   batch  = (const int*)d_in[21];
    float* out = (float*)d_out;

    k_encode<<<(N_NODES + 255) / 256, 256>>>(nf, enc_W, enc_b);
    k_edgehid<<<(N_EDGES + 255) / 256, 256>>>(ef, e_W1, e_b1);
    k_gemmA<<<dim3(1024 / GBN, N_EDGES / GBM), 256>>>(e_W2, e_b2);

    for (int r = 0; r < 3; r++) {
        k_zero_m<<<(N_NODES * H + 255) / 256, 256>>>();
        k_message<<<(N_EDGES * 32) / 256, 256>>>(eidx);
        k_gru<<<(N_NODES + 255) / 256, 256>>>(gWih, gWhh, gbih, gbhh);
    }

    k_zero_s2s<<<(NG * H + 255) / 256, 256>>>();
    k_offs<<<(N_NODES + 255) / 256, 256>>>(batch);

    for (int s = 0; s < 4; s++) {
        k_attend<<<(NG * 32 + 255) / 256, 256>>>();
        k_lstm<<<(NG + 255) / 256, 256>>>(lWih, lWhh, lbih, lbhh);
    }

    k_output<<<(NG + 255) / 256, 256>>>(oW1, ob1, oW2, ob2, out);
}

// round 3
// speedup vs baseline: 1.6517x; 1.6517x over previous
#include <cuda_runtime.h>
#include <cuda_fp16.h>
#include <math_constants.h>

#define N_NODES 100000
#define N_EDGES 200000
#define NG      2000
#define H       32

typedef unsigned long long ull;

// ---------------- device scratch (alloc-free) ----------------
__device__ float g_h[N_NODES * H];                 // node hidden     12.8 MB
__device__ float g_m[N_NODES * H];                 // aggregated msgs 12.8 MB
__device__ float g_r[N_EDGES * 64];                // edge hidden     51.2 MB
__device__ uint4 g_Abuf[(size_t)N_EDGES * 128];    // edge matrices fp16, 409.6 MB (16B aligned)
__device__ float g_sh[NG * H];                     // set2set h
__device__ float g_sc[NG * H];                     // set2set c
__device__ float g_rr[NG * H];                     // readout r
__device__ int   g_offs[NG + 1];                   // graph segment offsets

// ---------------- helpers ----------------
__device__ __forceinline__ ull pk2(float x) {
    ull r; asm("mov.b64 %0, {%1, %1};" : "=l"(r) : "f"(x)); return r;
}
__device__ __forceinline__ ull pkab(float lo, float hi) {
    ull r; asm("mov.b64 %0, {%1, %2};" : "=l"(r) : "f"(lo), "f"(hi)); return r;
}
__device__ __forceinline__ ull fma2(ull a, ull b, ull c) {
    ull d; asm("fma.rn.f32x2 %0, %1, %2, %3;" : "=l"(d) : "l"(a), "l"(b), "l"(c)); return d;
}
__device__ __forceinline__ void unpk2(ull v, float& lo, float& hi) {
    asm("mov.b64 {%0, %1}, %2;" : "=f"(lo), "=f"(hi) : "l"(v));
}
__device__ __forceinline__ float warpMax(float v) {
    #pragma unroll
    for (int o = 16; o > 0; o >>= 1) v = fmaxf(v, __shfl_xor_sync(0xffffffffu, v, o));
    return v;
}
__device__ __forceinline__ float warpSum(float v) {
    #pragma unroll
    for (int o = 16; o > 0; o >>= 1) v += __shfl_xor_sync(0xffffffffu, v, o);
    return v;
}
__device__ __forceinline__ float sigm(float x) { return 1.0f / (1.0f + expf(-x)); }

// ---------------- zero kernels ----------------
__global__ void k_zero_m() {
    int i = blockIdx.x * blockDim.x + threadIdx.x;
    if (i < N_NODES * 8) ((float4*)g_m)[i] = make_float4(0.f, 0.f, 0.f, 0.f);
}
__global__ void k_zero_s2s() {
    int i = blockIdx.x * blockDim.x + threadIdx.x;
    if (i < NG * H) { g_sh[i] = 0.0f; g_sc[i] = 0.0f; g_rr[i] = 0.0f; }
}

// ---------------- encoder: h = nf @ enc_W + enc_b ----------------
__global__ void k_encode(const float* __restrict__ nf, const float* __restrict__ W,
                         const float* __restrict__ b) {
    __shared__ float sW[16 * 32];
    __shared__ float sb[32];
    int t = threadIdx.x;
    for (int i = t; i < 512; i += 256) sW[i] = W[i];
    if (t < 32) sb[t] = b[t];
    __syncthreads();
    int n = blockIdx.x * blockDim.x + t;
    if (n >= N_NODES) return;
    float x[16];
    const float4* p = (const float4*)(nf + (long long)n * 16);
    #pragma unroll
    for (int q = 0; q < 4; q++) {
        float4 v = p[q];
        x[q*4+0] = v.x; x[q*4+1] = v.y; x[q*4+2] = v.z; x[q*4+3] = v.w;
    }
    #pragma unroll
    for (int c = 0; c < 32; c++) {
        float acc = sb[c];
        #pragma unroll
        for (int d = 0; d < 16; d++) acc += x[d] * sW[d * 32 + c];
        g_h[n * 32 + c] = acc;
    }
}

// ---------------- edge hidden: r = relu(ef @ e_W1 + e_b1) ----------------
__global__ void k_edgehid(const float* __restrict__ ef, const float* __restrict__ W,
                          const float* __restrict__ b) {
    __shared__ float sW[8 * 64];
    __shared__ float sb[64];
    int t = threadIdx.x;
    for (int i = t; i < 512; i += 256) sW[i] = W[i];
    if (t < 64) sb[t] = b[t];
    __syncthreads();
    int e = blockIdx.x * blockDim.x + t;
    if (e >= N_EDGES) return;
    float x[8];
    const float4* p = (const float4*)(ef + (long long)e * 8);
    float4 v0 = p[0], v1 = p[1];
    x[0]=v0.x; x[1]=v0.y; x[2]=v0.z; x[3]=v0.w;
    x[4]=v1.x; x[5]=v1.y; x[6]=v1.z; x[7]=v1.w;
    #pragma unroll
    for (int c = 0; c < 64; c++) {
        float acc = sb[c];
        #pragma unroll
        for (int d = 0; d < 8; d++) acc += x[d] * sW[d * 64 + c];
        g_r[(long long)e * 64 + c] = fmaxf(acc, 0.0f);
    }
}

// ---------------- A GEMM: A[E,1024] = r[E,64] @ W2[64,1024] + b2 (fp16 out) ----
#define GBM 64
#define GBN 256
#define GBK 32
__global__ void __launch_bounds__(256) k_gemmA(const float* __restrict__ W2,
                                               const float* __restrict__ b2) {
    __shared__ float Rs[GBK][GBM];   // [k][m]  8 KB
    __shared__ float Ws[GBK][GBN];   // [k][n] 32 KB
    int t  = threadIdx.x;
    int e0 = blockIdx.y * GBM;
    int n0 = blockIdx.x * GBN;
    int tm = t >> 6;
    int tn = t & 63;
    int tm16 = tm * 16;

    ull acc[8][4];
    #pragma unroll
    for (int j = 0; j < 4; j++) {
        ull bd = pk2(__ldg(&b2[n0 + tn + 64 * j]));
        #pragma unroll
        for (int mi = 0; mi < 8; mi++) acc[mi][j] = bd;
    }

    #pragma unroll
    for (int kt = 0; kt < 2; kt++) {
        int k0 = kt * GBK;
        #pragma unroll
        for (int i = 0; i < 2; i++) {
            int idx = t + 256 * i;
            int m   = idx >> 3;
            int kq  = idx & 7;
            float4 v = *(const float4*)&g_r[(long long)(e0 + m) * 64 + k0 + kq * 4];
            Rs[kq*4+0][m] = v.x; Rs[kq*4+1][m] = v.y;
            Rs[kq*4+2][m] = v.z; Rs[kq*4+3][m] = v.w;
        }
        #pragma unroll
        for (int i = 0; i < 8; i++) {
            int idx = t + 256 * i;
            int k   = idx >> 6;
            int nq  = idx & 63;
            *(float4*)&Ws[k][nq * 4] =
                *(const float4*)&W2[(long long)(k0 + k) * 1024 + n0 + nq * 4];
        }
        __syncthreads();

        #pragma unroll
        for (int k = 0; k < GBK; k++) {
            ull av[8];
            const ulonglong2* ap = (const ulonglong2*)&Rs[k][tm16];
            ulonglong2 a0 = ap[0], a1 = ap[1], a2 = ap[2], a3 = ap[3];
            av[0]=a0.x; av[1]=a0.y; av[2]=a1.x; av[3]=a1.y;
            av[4]=a2.x; av[5]=a2.y; av[6]=a3.x; av[7]=a3.y;
            #pragma unroll
            for (int j = 0; j < 4; j++) {
                ull bd = pk2(Ws[k][tn + 64 * j]);
                #pragma unroll
                for (int mi = 0; mi < 8; mi++) acc[mi][j] = fma2(av[mi], bd, acc[mi][j]);
            }
        }
        __syncthreads();
    }

    __half* gA = (__half*)g_Abuf;
    #pragma unroll
    for (int mi = 0; mi < 8; mi++) {
        int row = e0 + tm16 + 2 * mi;
        #pragma unroll
        for (int j = 0; j < 4; j++) {
            float lo, hi;
            unpk2(acc[mi][j], lo, hi);
            int col = n0 + tn + 64 * j;
            gA[(size_t)row * 1024 + col]       = __float2half_rn(lo);
            gA[(size_t)(row + 1) * 1024 + col] = __float2half_rn(hi);
        }
    }
}

// ---------------- message pass: m[tgt] += A[e] @ h[src] (fp16 A) ----------------
__global__ void __launch_bounds__(256) k_message(const int* __restrict__ ei) {
    int lane = threadIdx.x & 31;
    int e = (blockIdx.x * blockDim.x + threadIdx.x) >> 5;
    if (e >= N_EDGES) return;
    int src = ei[e];
    int tgt = ei[N_EDGES + e];
    float hv = g_h[src * 32 + lane];
    const uint4* Ar = g_Abuf + (size_t)e * 128 + lane * 4;
    float acc = 0.0f;
    #pragma unroll
    for (int u = 0; u < 4; u++) {
        uint4 a = Ar[u];
        float2 f0 = __half22float2(*(__half2*)&a.x);
        float2 f1 = __half22float2(*(__half2*)&a.y);
        float2 f2 = __half22float2(*(__half2*)&a.z);
        float2 f3 = __half22float2(*(__half2*)&a.w);
        acc += f0.x * __shfl_sync(0xffffffffu, hv, 8*u+0);
        acc += f0.y * __shfl_sync(0xffffffffu, hv, 8*u+1);
        acc += f1.x * __shfl_sync(0xffffffffu, hv, 8*u+2);
        acc += f1.y * __shfl_sync(0xffffffffu, hv, 8*u+3);
        acc += f2.x * __shfl_sync(0xffffffffu, hv, 8*u+4);
        acc += f2.y * __shfl_sync(0xffffffffu, hv, 8*u+5);
        acc += f3.x * __shfl_sync(0xffffffffu, hv, 8*u+6);
        acc += f3.y * __shfl_sync(0xffffffffu, hv, 8*u+7);
    }
    atomicAdd(&g_m[tgt * 32 + lane], acc);
}

// ---------------- GRU cell (f32x2 k-pairs, weights pre-packed in smem) --------
__global__ void __launch_bounds__(256) k_gru(const float* __restrict__ Wih,
                                             const float* __restrict__ Whh,
                                             const float* __restrict__ bih,
                                             const float* __restrict__ bhh) {
    __shared__ ull sWi2[3 * 16 * 32];   // [gate][k2][c] pairs, 12 KB
    __shared__ ull sWh2[3 * 16 * 32];   // 12 KB
    __shared__ float sbi[96];
    __shared__ float sbh[96];
    int t = threadIdx.x;
    for (int i = t; i < 1536; i += 256) {
        int g  = i >> 9;
        int k2 = (i >> 5) & 15;
        int c  = i & 31;
        int k  = g * 32 + 2 * k2;
        sWi2[i] = pkab(Wih[k * 32 + c], Wih[(k + 1) * 32 + c]);
        sWh2[i] = pkab(Whh[k * 32 + c], Whh[(k + 1) * 32 + c]);
    }
    if (t < 96) { sbi[t] = bih[t]; sbh[t] = bhh[t]; }
    __syncthreads();
    int n = blockIdx.x * blockDim.x + t;
    if (n >= N_NODES) return;

    float mv[32], hv[32];
    const float4* mp = (const float4*)&g_m[n * 32];
    const float4* hp = (const float4*)&g_h[n * 32];
    #pragma unroll
    for (int q = 0; q < 8; q++) {
        float4 a = mp[q]; mv[q*4]=a.x; mv[q*4+1]=a.y; mv[q*4+2]=a.z; mv[q*4+3]=a.w;
        float4 b = hp[q]; hv[q*4]=b.x; hv[q*4+1]=b.y; hv[q*4+2]=b.z; hv[q*4+3]=b.w;
    }

    #pragma unroll 1
    for (int k2 = 0; k2 < 16; k2++) {
        int k = 2 * k2;
        ull accr = pkab(sbi[k] + sbh[k], sbi[k + 1] + sbh[k + 1]);
        ull accz = pkab(sbi[32 + k] + sbh[32 + k], sbi[33 + k] + sbh[33 + k]);
        ull accn = pkab(sbi[64 + k], sbi[65 + k]);
        ull acch = pkab(sbh[64 + k], sbh[65 + k]);
        const ull* wir = &sWi2[(0 * 16 + k2) * 32];
        const ull* wiz = &sWi2[(1 * 16 + k2) * 32];
        const ull* win = &sWi2[(2 * 16 + k2) * 32];
        const ull* whr = &sWh2[(0 * 16 + k2) * 32];
        const ull* whz = &sWh2[(1 * 16 + k2) * 32];
        const ull* whn = &sWh2[(2 * 16 + k2) * 32];
        #pragma unroll
        for (int c = 0; c < 32; c++) {
            ull pm = pk2(mv[c]);
            ull ph = pk2(hv[c]);
            accr = fma2(pm, wir[c], accr);
            accr = fma2(ph, whr[c], accr);
            accz = fma2(pm, wiz[c], accz);
            accz = fma2(ph, whz[c], accz);
            accn = fma2(pm, win[c], accn);
            acch = fma2(ph, whn[c], acch);
        }
        float rlo, rhi, zlo, zhi, nlo, nhi, hlo, hhi;
        unpk2(accr, rlo, rhi);
        unpk2(accz, zlo, zhi);
        unpk2(accn, nlo, nhi);
        unpk2(acch, hlo, hhi);
        float2 hold = *(const float2*)&g_h[n * 32 + k];   // L1 hit
        float r0 = sigm(rlo), z0 = sigm(zlo);
        float n0 = tanhf(nlo + r0 * hlo);
        float r1 = sigm(rhi), z1 = sigm(zhi);
        float n1 = tanhf(nhi + r1 * hhi);
        float2 hnew;
        hnew.x = (1.0f - z0) * n0 + z0 * hold.x;
        hnew.y = (1.0f - z1) * n1 + z1 * hold.y;
        *(float2*)&g_h[n * 32 + k] = hnew;
    }
}

// ---------------- graph segment offsets (batch_indices sorted) ----------------
__global__ void k_offs(const int* __restrict__ batch) {
    int n = blockIdx.x * blockDim.x + threadIdx.x;
    if (n >= N_NODES) return;
    int b = batch[n];
    int prev = (n == 0) ? -1 : batch[n - 1];
    for (int g = prev + 1; g <= b; g++) g_offs[g] = n;
    if (n == N_NODES - 1)
        for (int g = b + 1; g <= NG; g++) g_offs[g] = N_NODES;
}

// ---------------- Set2Set attention + readout (online softmax, warp/graph) ----
__global__ void __launch_bounds__(256) k_attend() {
    int lane = threadIdx.x & 31;
    int g = (blockIdx.x * blockDim.x + threadIdx.x) >> 5;
    if (g >= NG) return;
    int s = g_offs[g], tEnd = g_offs[g + 1];
    float q = g_sh[g * 32 + lane];
    float maxv = -CUDART_INF_F, denom = 0.0f, racc = 0.0f;

    for (int base = s; base < tEnd; base += 32) {
        int n = base + lane;
        bool act = n < tEnd;
        int nn = act ? n : s;
        float rv[32];
        const float4* hp4 = (const float4*)&g_h[nn * 32];
        #pragma unroll
        for (int q4 = 0; q4 < 8; q4++) {
            float4 v = hp4[q4];
            rv[q4*4] = v.x; rv[q4*4+1] = v.y; rv[q4*4+2] = v.z; rv[q4*4+3] = v.w;
        }
        float ev = 0.0f;
        #pragma unroll
        for (int j = 0; j < 32; j++)
            ev += rv[j] * __shfl_sync(0xffffffffu, q, j);
        float e_n = act ? ev : -CUDART_INF_F;
        float cm = warpMax(e_n);
        float nm = fmaxf(maxv, cm);
        float scale = (maxv == -CUDART_INF_F) ? 0.0f : expf(maxv - nm);
        float p = act ? expf(e_n - nm) : 0.0f;
        float ps = warpSum(p);
        denom = denom * scale + ps;
        racc *= scale;
        maxv = nm;
        int cnt = min(32, tEnd - base);
        for (int n2 = 0; n2 < cnt; n2++) {
            float pn = __shfl_sync(0xffffffffu, p, n2);
            racc += pn * g_h[(base + n2) * 32 + lane];
        }
    }
    g_rr[g * 32 + lane] = (denom > 0.0f) ? (racc / denom) : 0.0f;
}

// ---------------- Set2Set LSTM step (fused mini-GEMM, 64 graphs/block) --------
// G = [sh|rr] @ Wih^T + sh @ Whh^T  -> pointwise LSTM.
__global__ void __launch_bounds__(256) k_lstm(const float* __restrict__ Wih,
                                              const float* __restrict__ Whh,
                                              const float* __restrict__ bih,
                                              const float* __restrict__ bhh) {
    __shared__ float sx[64 * 64];     // [g][c], c<32: sh, c>=32: rr   16 KB
    __shared__ float sW[48 * 128];    // [c][kk] chunk                 24 KB
    int t  = threadIdx.x;
    int g0 = blockIdx.x * 64;
    int k  = t & 31;
    int rg = t >> 5;

    for (int i = t; i < 64 * 64; i += 256) {
        int g = i >> 6, c = i & 63;
        int gg = g0 + g;
        float v = 0.0f;
        if (gg < NG) v = (c < 32) ? g_sh[gg * 32 + c] : g_rr[gg * 32 + (c - 32)];
        sx[i] = v;
    }

    float acc[8][4];
    #pragma unroll
    for (int r = 0; r < 8; r++)
        #pragma unroll
        for (int j = 0; j < 4; j++) acc[r][j] = 0.0f;

    #pragma unroll 1
    for (int kc = 0; kc < 2; kc++) {
        __syncthreads();
        for (int i = t; i < 48 * 128; i += 256) {
            int c  = kc * 48 + (i >> 7);
            int kk = i & 127;
            sW[i] = (c < 64) ? Wih[kk * 64 + c] : Whh[kk * 32 + (c - 64)];
        }
        __syncthreads();
        for (int cc = 0; cc < 48; cc++) {
            int c  = kc * 48 + cc;
            int cx = (c < 64) ? c : (c - 64);
            float b0 = sW[cc * 128 + k];
            float b1 = sW[cc * 128 + 32 + k];
            float b2v = sW[cc * 128 + 64 + k];
            float b3 = sW[cc * 128 + 96 + k];
            #pragma unroll
            for (int r = 0; r < 8; r++) {
                float a = sx[(rg * 8 + r) * 64 + cx];
                acc[r][0] += a * b0;
                acc[r][1] += a * b1;
                acc[r][2] += a * b2v;
                acc[r][3] += a * b3;
            }
        }
    }

    float bi0 = __ldg(&bih[k])      + __ldg(&bhh[k]);
    float bf  = __ldg(&bih[32 + k]) + __ldg(&bhh[32 + k]);
    float bg  = __ldg(&bih[64 + k]) + __ldg(&bhh[64 + k]);
    float bo  = __ldg(&bih[96 + k]) + __ldg(&bhh[96 + k]);
    #pragma unroll
    for (int r = 0; r < 8; r++) {
        int gg = g0 + rg * 8 + r;
        if (gg >= NG) break;
        float i_ = sigm(acc[r][0] + bi0);
        float f_ = sigm(acc[r][1] + bf);
        float gv = tanhf(acc[r][2] + bg);
        float o_ = sigm(acc[r][3] + bo);
        float cn = f_ * g_sc[gg * 32 + k] + i_ * gv;
        g_sc[gg * 32 + k] = cn;
        g_sh[gg * 32 + k] = o_ * tanhf(cn);
    }
}

// ---------------- output head ----------------
__global__ void k_output(const float* __restrict__ W1, const float* __restrict__ b1,
                         const float* __restrict__ W2, const float* __restrict__ b2,
                         float* __restrict__ out) {
    int g = blockIdx.x * blockDim.x + threadIdx.x;
    if (g >= NG) return;
    float emb[64];
    #pragma unroll
    for (int c = 0; c < 32; c++) {
        emb[c]      = g_sh[g * 32 + c];
        emb[32 + c] = g_rr[g * 32 + c];
    }
    float hid[32];
    #pragma unroll
    for (int c = 0; c < 32; c++) {
        float acc = __ldg(&b1[c]);
        #pragma unroll
        for (int d = 0; d < 64; d++) acc += emb[d] * __ldg(&W1[d * 32 + c]);
        hid[c] = fmaxf(acc, 0.0f);
    }
    #pragma unroll
    for (int kk = 0; kk < 3; kk++) {
        float acc = __ldg(&b2[kk]);
        #pragma unroll
        for (int c = 0; c < 32; c++) acc += hid[c] * __ldg(&W2[c * 3 + kk]);
        out[g * 3 + kk] = acc;
    }
}

// ---------------- launch ----------------
extern "C" void kernel_launch(void* const* d_in, const int* in_sizes, int n_in,
                              void* d_out, int out_size) {
    const float* nf     = (const float*)d_in[0];
    const float* ef     = (const float*)d_in[1];
    const float* enc_W  = (const float*)d_in[2];
    const float* enc_b  = (const float*)d_in[3];
    const float* e_W1   = (const float*)d_in[4];
    const float* e_b1   = (const float*)d_in[5];
    const float* e_W2   = (const float*)d_in[6];
    const float* e_b2   = (const float*)d_in[7];
    const float* gWih   = (const float*)d_in[8];
    const float* gWhh   = (const float*)d_in[9];
    const float* gbih   = (const float*)d_in[10];
    const float* gbhh   = (const float*)d_in[11];
    const float* lWih   = (const float*)d_in[12];
    const float* lWhh   = (const float*)d_in[13];
    const float* lbih   = (const float*)d_in[14];
    const float* lbhh   = (const float*)d_in[15];
    const float* oW1    = (const float*)d_in[16];
    const float* ob1    = (const float*)d_in[17];
    const float* oW2    = (const float*)d_in[18];
    const float* ob2    = (const float*)d_in[19];
    const int*   eidx   = (const int*)d_in[20];
    const int*   batch  = (const int*)d_in[21];
    float* out = (float*)d_out;

    k_encode<<<(N_NODES + 255) / 256, 256>>>(nf, enc_W, enc_b);
    k_edgehid<<<(N_EDGES + 255) / 256, 256>>>(ef, e_W1, e_b1);
    k_gemmA<<<dim3(1024 / GBN, N_EDGES / GBM), 256>>>(e_W2, e_b2);

    for (int r = 0; r < 3; r++) {
        k_zero_m<<<(N_NODES * 8 + 255) / 256, 256>>>();
        k_message<<<(N_EDGES * 32) / 256, 256>>>(eidx);
        k_gru<<<(N_NODES + 255) / 256, 256>>>(gWih, gWhh, gbih, gbhh);
    }

    k_zero_s2s<<<(NG * H + 255) / 256, 256>>>();
    k_offs<<<(N_NODES + 255) / 256, 256>>>(batch);

    for (int s = 0; s < 4; s++) {
        k_attend<<<(NG * 32 + 255) / 256, 256>>>();
        k_lstm<<<(NG + 63) / 64, 256>>>(lWih, lWhh, lbih, lbhh);
    }

    k_output<<<(NG + 255) / 256, 256>>>(oW1, ob1, oW2, ob2, out);
}

// round 5
// speedup vs baseline: 2.4789x; 1.5008x over previous
#include <cuda_runtime.h>
#include <cuda_fp16.h>
#include <math_constants.h>

#define N_NODES 100000
#define N_EDGES 200000
#define NG      2000
#define H       32

typedef unsigned long long ull;

// ---------------- device scratch (alloc-free) ----------------
__device__ float  g_h[N_NODES * H];                 // node hidden     12.8 MB
__device__ float  g_m[N_NODES * H];                 // aggregated msgs 12.8 MB
__device__ __half g_rh[(size_t)N_EDGES * 64];       // edge hidden fp16 25.6 MB
__device__ uint4  g_Abuf[(size_t)N_EDGES * 128];    // edge matrices fp16, 409.6 MB
__device__ float  g_sh[NG * H];                     // set2set h
__device__ float  g_sc[NG * H];                     // set2set c
__device__ float  g_rr[NG * H];                     // readout r
__device__ int    g_offs[NG + 1];                   // graph segment offsets

// ---------------- helpers ----------------
__device__ __forceinline__ ull pk2(float x) {
    ull r; asm("mov.b64 %0, {%1, %1};" : "=l"(r) : "f"(x)); return r;
}
__device__ __forceinline__ ull pkab(float lo, float hi) {
    ull r; asm("mov.b64 %0, {%1, %2};" : "=l"(r) : "f"(lo), "f"(hi)); return r;
}
__device__ __forceinline__ ull fma2(ull a, ull b, ull c) {
    ull d; asm("fma.rn.f32x2 %0, %1, %2, %3;" : "=l"(d) : "l"(a), "l"(b), "l"(c)); return d;
}
__device__ __forceinline__ void unpk2(ull v, float& lo, float& hi) {
    asm("mov.b64 {%0, %1}, %2;" : "=f"(lo), "=f"(hi) : "l"(v));
}
__device__ __forceinline__ float warpMax(float v) {
    #pragma unroll
    for (int o = 16; o > 0; o >>= 1) v = fmaxf(v, __shfl_xor_sync(0xffffffffu, v, o));
    return v;
}
__device__ __forceinline__ float warpSum(float v) {
    #pragma unroll
    for (int o = 16; o > 0; o >>= 1) v += __shfl_xor_sync(0xffffffffu, v, o);
    return v;
}
__device__ __forceinline__ float sigm(float x) { return 1.0f / (1.0f + expf(-x)); }

// ---------------- zero kernels ----------------
__global__ void k_zero_m() {
    int i = blockIdx.x * blockDim.x + threadIdx.x;
    if (i < N_NODES * 8) ((float4*)g_m)[i] = make_float4(0.f, 0.f, 0.f, 0.f);
}
__global__ void k_zero_s2s() {
    int i = blockIdx.x * blockDim.x + threadIdx.x;
    if (i < NG * H) { g_sh[i] = 0.0f; g_sc[i] = 0.0f; g_rr[i] = 0.0f; }
}

// ---------------- encoder: h = nf @ enc_W + enc_b ----------------
__global__ void k_encode(const float* __restrict__ nf, const float* __restrict__ W,
                         const float* __restrict__ b) {
    __shared__ float sW[16 * 32];
    __shared__ float sb[32];
    int t = threadIdx.x;
    for (int i = t; i < 512; i += 256) sW[i] = W[i];
    if (t < 32) sb[t] = b[t];
    __syncthreads();
    int n = blockIdx.x * blockDim.x + t;
    if (n >= N_NODES) return;
    float x[16];
    const float4* p = (const float4*)(nf + (long long)n * 16);
    #pragma unroll
    for (int q = 0; q < 4; q++) {
        float4 v = p[q];
        x[q*4+0] = v.x; x[q*4+1] = v.y; x[q*4+2] = v.z; x[q*4+3] = v.w;
    }
    #pragma unroll
    for (int c = 0; c < 32; c++) {
        float acc = sb[c];
        #pragma unroll
        for (int d = 0; d < 16; d++) acc += x[d] * sW[d * 32 + c];
        g_h[n * 32 + c] = acc;
    }
}

// ---------------- edge hidden: rh = fp16(relu(ef @ e_W1 + e_b1)) ----------------
__global__ void k_edgehid(const float* __restrict__ ef, const float* __restrict__ W,
                          const float* __restrict__ b) {
    __shared__ float sW[8 * 64];
    __shared__ float sb[64];
    int t = threadIdx.x;
    for (int i = t; i < 512; i += 256) sW[i] = W[i];
    if (t < 64) sb[t] = b[t];
    __syncthreads();
    int e = blockIdx.x * blockDim.x + t;
    if (e >= N_EDGES) return;
    float x[8];
    const float4* p = (const float4*)(ef + (long long)e * 8);
    float4 v0 = p[0], v1 = p[1];
    x[0]=v0.x; x[1]=v0.y; x[2]=v0.z; x[3]=v0.w;
    x[4]=v1.x; x[5]=v1.y; x[6]=v1.z; x[7]=v1.w;
    float o[64];
    #pragma unroll
    for (int c = 0; c < 64; c++) {
        float acc = sb[c];
        #pragma unroll
        for (int d = 0; d < 8; d++) acc += x[d] * sW[d * 64 + c];
        o[c] = fmaxf(acc, 0.0f);
    }
    __half2* dst = (__half2*)&g_rh[(size_t)e * 64];
    #pragma unroll
    for (int c2 = 0; c2 < 32; c2++)
        dst[c2] = __floats2half2_rn(o[2 * c2], o[2 * c2 + 1]);
}

// ---------------- A GEMM (tensor cores): A[E,1024] = rh[E,64] @ W2[64,1024] + b2
// fp16 in, fp32 accum, fp16 out. BM=128, BN=128, K=64 one-shot.
// 8 warps: warpM = (wid&1)*64, warpN = (wid>>1)*32; warp tile 64x32.
// Rs[m][k], Wt[n][k] fp16, rows padded to 72 halves (144B stride -> ldmatrix
// 8x8 rows hit distinct bank groups, conflict-free).
#define ROWP 72
__global__ void __launch_bounds__(256) k_gemmA(const float* __restrict__ W2,
                                               const float* __restrict__ b2) {
    __shared__ __half Rs[128 * ROWP];   // 18 KB
    __shared__ __half Wt[128 * ROWP];   // 18 KB
    int t    = threadIdx.x;
    int lane = t & 31;
    int wid  = t >> 5;
    int e0   = blockIdx.y * 128;
    int n0   = blockIdx.x * 128;
    int warpM = (wid & 1) * 64;
    int warpN = (wid >> 1) * 32;

    // load rh tile [128 x 64] fp16 (uint4 = 8 halves)
    #pragma unroll
    for (int i = 0; i < 4; i++) {
        int g   = t + 256 * i;          // 1024 granules
        int row = g >> 3;
        int kg  = g & 7;
        uint4 v = make_uint4(0u, 0u, 0u, 0u);
        int e = e0 + row;
        if (e < N_EDGES) v = *(const uint4*)&g_rh[(size_t)e * 64 + kg * 8];
        *(uint4*)&Rs[row * ROWP + kg * 8] = v;
    }
    // load + transpose W2 tile: Wt[n][k] = fp16(W2[k][n0+n])
    #pragma unroll
    for (int i = 0; i < 32; i++) {
        int idx = t + 256 * i;          // 8192 elements
        int n   = idx & 127;
        int k   = idx >> 7;
        Wt[n * ROWP + k] = __float2half_rn(W2[k * 1024 + n0 + n]);
    }
    __syncthreads();

    // fragment addresses
    int aRow = warpM + (lane & 15);
    int aColB = (lane >> 4) << 3;
    int bRow = warpN + (lane & 7) + ((lane >> 4) << 3);
    int bColB = ((lane >> 3) & 1) << 3;

    float acc[4][4][4];
    #pragma unroll
    for (int mt = 0; mt < 4; mt++)
        #pragma unroll
        for (int nt = 0; nt < 4; nt++)
            #pragma unroll
            for (int q = 0; q < 4; q++) acc[mt][nt][q] = 0.0f;

    #pragma unroll
    for (int ks = 0; ks < 4; ks++) {
        int k0 = ks * 16;
        unsigned a[4][4];
        #pragma unroll
        for (int mt = 0; mt < 4; mt++) {
            unsigned addr = (unsigned)__cvta_generic_to_shared(
                &Rs[(aRow + mt * 16) * ROWP + k0 + aColB]);
            asm volatile("ldmatrix.sync.aligned.m8n8.x4.shared.b16 {%0,%1,%2,%3}, [%4];"
                         : "=r"(a[mt][0]), "=r"(a[mt][1]), "=r"(a[mt][2]), "=r"(a[mt][3])
                         : "r"(addr));
        }
        unsigned bf[4][2];
        #pragma unroll
        for (int p = 0; p < 2; p++) {
            unsigned addr = (unsigned)__cvta_generic_to_shared(
                &Wt[(bRow + p * 16) * ROWP + k0 + bColB]);
            asm volatile("ldmatrix.sync.aligned.m8n8.x4.shared.b16 {%0,%1,%2,%3}, [%4];"
                         : "=r"(bf[2*p][0]), "=r"(bf[2*p][1]),
                           "=r"(bf[2*p+1][0]), "=r"(bf[2*p+1][1])
                         : "r"(addr));
        }
        #pragma unroll
        for (int mt = 0; mt < 4; mt++)
            #pragma unroll
            for (int nt = 0; nt < 4; nt++) {
                asm volatile(
                    "mma.sync.aligned.m16n8k16.row.col.f32.f16.f16.f32 "
                    "{%0,%1,%2,%3}, {%4,%5,%6,%7}, {%8,%9}, {%0,%1,%2,%3};"
                    : "+f"(acc[mt][nt][0]), "+f"(acc[mt][nt][1]),
                      "+f"(acc[mt][nt][2]), "+f"(acc[mt][nt][3])
                    : "r"(a[mt][0]), "r"(a[mt][1]), "r"(a[mt][2]), "r"(a[mt][3]),
                      "r"(bf[nt][0]), "r"(bf[nt][1]));
            }
    }

    // epilogue: +bias, fp16 store
    __half* gA = (__half*)g_Abuf;
    int r0base = e0 + warpM + (lane >> 2);
    #pragma unroll
    for (int nt = 0; nt < 4; nt++) {
        int col = n0 + warpN + nt * 8 + (lane & 3) * 2;
        float2 bb = *(const float2*)&b2[col];
        #pragma unroll
        for (int mt = 0; mt < 4; mt++) {
            int r0 = r0base + mt * 16;
            if (r0 < N_EDGES)
                *(__half2*)&gA[(size_t)r0 * 1024 + col] =
                    __floats2half2_rn(acc[mt][nt][0] + bb.x, acc[mt][nt][1] + bb.y);
            int r1 = r0 + 8;
            if (r1 < N_EDGES)
                *(__half2*)&gA[(size_t)r1 * 1024 + col] =
                    __floats2half2_rn(acc[mt][nt][2] + bb.x, acc[mt][nt][3] + bb.y);
        }
    }
}

// ---------------- message pass: m[tgt] += A[e] @ h[src] (fp16 A) ----------------
__global__ void __launch_bounds__(256) k_message(const int* __restrict__ ei) {
    int lane = threadIdx.x & 31;
    int e = (blockIdx.x * blockDim.x + threadIdx.x) >> 5;
    if (e >= N_EDGES) return;
    int src = ei[e];
    int tgt = ei[N_EDGES + e];
    float hv = g_h[src * 32 + lane];
    const uint4* Ar = g_Abuf + (size_t)e * 128 + lane * 4;
    float acc = 0.0f;
    #pragma unroll
    for (int u = 0; u < 4; u++) {
        uint4 a = Ar[u];
        float2 f0 = __half22float2(*(__half2*)&a.x);
        float2 f1 = __half22float2(*(__half2*)&a.y);
        float2 f2 = __half22float2(*(__half2*)&a.z);
        float2 f3 = __half22float2(*(__half2*)&a.w);
        acc += f0.x * __shfl_sync(0xffffffffu, hv, 8*u+0);
        acc += f0.y * __shfl_sync(0xffffffffu, hv, 8*u+1);
        acc += f1.x * __shfl_sync(0xffffffffu, hv, 8*u+2);
        acc += f1.y * __shfl_sync(0xffffffffu, hv, 8*u+3);
        acc += f2.x * __shfl_sync(0xffffffffu, hv, 8*u+4);
        acc += f2.y * __shfl_sync(0xffffffffu, hv, 8*u+5);
        acc += f3.x * __shfl_sync(0xffffffffu, hv, 8*u+6);
        acc += f3.y * __shfl_sync(0xffffffffu, hv, 8*u+7);
    }
    atomicAdd(&g_m[tgt * 32 + lane], acc);
}

// ---------------- GRU cell (f32x2 k-pairs); zeroes g_m for next round --------
__global__ void __launch_bounds__(256) k_gru(const float* __restrict__ Wih,
                                             const float* __restrict__ Whh,
                                             const float* __restrict__ bih,
                                             const float* __restrict__ bhh) {
    __shared__ ull sWi2[3 * 16 * 32];
    __shared__ ull sWh2[3 * 16 * 32];
    __shared__ float sbi[96];
    __shared__ float sbh[96];
    int t = threadIdx.x;
    for (int i = t; i < 1536; i += 256) {
        int g  = i >> 9;
        int k2 = (i >> 5) & 15;
        int c  = i & 31;
        int k  = g * 32 + 2 * k2;
        sWi2[i] = pkab(Wih[k * 32 + c], Wih[(k + 1) * 32 + c]);
        sWh2[i] = pkab(Whh[k * 32 + c], Whh[(k + 1) * 32 + c]);
    }
    if (t < 96) { sbi[t] = bih[t]; sbh[t] = bhh[t]; }
    __syncthreads();
    int n = blockIdx.x * blockDim.x + t;
    if (n >= N_NODES) return;

    float mv[32], hv[32];
    const float4* mp = (const float4*)&g_m[n * 32];
    const float4* hp = (const float4*)&g_h[n * 32];
    #pragma unroll
    for (int q = 0; q < 8; q++) {
        float4 a = mp[q]; mv[q*4]=a.x; mv[q*4+1]=a.y; mv[q*4+2]=a.z; mv[q*4+3]=a.w;
        float4 b = hp[q]; hv[q*4]=b.x; hv[q*4+1]=b.y; hv[q*4+2]=b.z; hv[q*4+3]=b.w;
    }
    // zero m for the next round (fused; graph-replay safe: last round leaves m=0)
    float4* mz = (float4*)&g_m[n * 32];
    #pragma unroll
    for (int q = 0; q < 8; q++) mz[q] = make_float4(0.f, 0.f, 0.f, 0.f);

    #pragma unroll 1
    for (int k2 = 0; k2 < 16; k2++) {
        int k = 2 * k2;
        ull accr = pkab(sbi[k] + sbh[k], sbi[k + 1] + sbh[k + 1]);
        ull accz = pkab(sbi[32 + k] + sbh[32 + k], sbi[33 + k] + sbh[33 + k]);
        ull accn = pkab(sbi[64 + k], sbi[65 + k]);
        ull acch = pkab(sbh[64 + k], sbh[65 + k]);
        const ull* wir = &sWi2[(0 * 16 + k2) * 32];
        const ull* wiz = &sWi2[(1 * 16 + k2) * 32];
        const ull* win = &sWi2[(2 * 16 + k2) * 32];
        const ull* whr = &sWh2[(0 * 16 + k2) * 32];
        const ull* whz = &sWh2[(1 * 16 + k2) * 32];
        const ull* whn = &sWh2[(2 * 16 + k2) * 32];
        #pragma unroll
        for (int c = 0; c < 32; c++) {
            ull pm = pk2(mv[c]);
            ull ph = pk2(hv[c]);
            accr = fma2(pm, wir[c], accr);
            accr = fma2(ph, whr[c], accr);
            accz = fma2(pm, wiz[c], accz);
            accz = fma2(ph, whz[c], accz);
            accn = fma2(pm, win[c], accn);
            acch = fma2(ph, whn[c], acch);
        }
        float rlo, rhi, zlo, zhi, nlo, nhi, hlo, hhi;
        unpk2(accr, rlo, rhi);
        unpk2(accz, zlo, zhi);
        unpk2(accn, nlo, nhi);
        unpk2(acch, hlo, hhi);
        float r0 = sigm(rlo), z0 = sigm(zlo);
        float n0 = tanhf(nlo + r0 * hlo);
        float r1 = sigm(rhi), z1 = sigm(zhi);
        float n1 = tanhf(nhi + r1 * hhi);
        float2 hnew;
        hnew.x = (1.0f - z0) * n0 + z0 * hv[k];
        hnew.y = (1.0f - z1) * n1 + z1 * hv[k + 1];
        *(float2*)&g_h[n * 32 + k] = hnew;
    }
}

// ---------------- graph segment offsets (batch_indices sorted) ----------------
__global__ void k_offs(const int* __restrict__ batch) {
    int n = blockIdx.x * blockDim.x + threadIdx.x;
    if (n >= N_NODES) return;
    int b = batch[n];
    int prev = (n == 0) ? -1 : batch[n - 1];
    for (int g = prev + 1; g <= b; g++) g_offs[g] = n;
    if (n == N_NODES - 1)
        for (int g = b + 1; g <= NG; g++) g_offs[g] = N_NODES;
}

// ---------------- Set2Set attention + readout (online softmax, warp/graph) ----
__global__ void __launch_bounds__(256) k_attend() {
    int lane = threadIdx.x & 31;
    int g = (blockIdx.x * blockDim.x + threadIdx.x) >> 5;
    if (g >= NG) return;
    int s = g_offs[g], tEnd = g_offs[g + 1];
    float q = g_sh[g * 32 + lane];
    float maxv = -CUDART_INF_F, denom = 0.0f, racc = 0.0f;

    for (int base = s; base < tEnd; base += 32) {
        int n = base + lane;
        bool act = n < tEnd;
        int nn = act ? n : s;
        float rv[32];
        const float4* hp4 = (const float4*)&g_h[nn * 32];
        #pragma unroll
        for (int q4 = 0; q4 < 8; q4++) {
            float4 v = hp4[q4];
            rv[q4*4] = v.x; rv[q4*4+1] = v.y; rv[q4*4+2] = v.z; rv[q4*4+3] = v.w;
        }
        float ev = 0.0f;
        #pragma unroll
        for (int j = 0; j < 32; j++)
            ev += rv[j] * __shfl_sync(0xffffffffu, q, j);
        float e_n = act ? ev : -CUDART_INF_F;
        float cm = warpMax(e_n);
        float nm = fmaxf(maxv, cm);
        float scale = (maxv == -CUDART_INF_F) ? 0.0f : expf(maxv - nm);
        float p = act ? expf(e_n - nm) : 0.0f;
        float ps = warpSum(p);
        denom = denom * scale + ps;
        racc *= scale;
        maxv = nm;
        int cnt = min(32, tEnd - base);
        for (int n2 = 0; n2 < cnt; n2++) {
            float pn = __shfl_sync(0xffffffffu, p, n2);
            racc += pn * g_h[(base + n2) * 32 + lane];
        }
    }
    g_rr[g * 32 + lane] = (denom > 0.0f) ? (racc / denom) : 0.0f;
}

// ---------------- Set2Set LSTM step (fused mini-GEMM, 64 graphs/block) --------
__global__ void __launch_bounds__(256) k_lstm(const float* __restrict__ Wih,
                                              const float* __restrict__ Whh,
                                              const float* __restrict__ bih,
                                              const float* __restrict__ bhh) {
    __shared__ float sx[64 * 64];
    __shared__ float sW[48 * 128];
    int t  = threadIdx.x;
    int g0 = blockIdx.x * 64;
    int k  = t & 31;
    int rg = t >> 5;

    for (int i = t; i < 64 * 64; i += 256) {
        int g = i >> 6, c = i & 63;
        int gg = g0 + g;
        float v = 0.0f;
        if (gg < NG) v = (c < 32) ? g_sh[gg * 32 + c] : g_rr[gg * 32 + (c - 32)];
        sx[i] = v;
    }

    float acc[8][4];
    #pragma unroll
    for (int r = 0; r < 8; r++)
        #pragma unroll
        for (int j = 0; j < 4; j++) acc[r][j] = 0.0f;

    #pragma unroll 1
    for (int kc = 0; kc < 2; kc++) {
        __syncthreads();
        for (int i = t; i < 48 * 128; i += 256) {
            int c  = kc * 48 + (i >> 7);
            int kk = i & 127;
            sW[i] = (c < 64) ? Wih[kk * 64 + c] : Whh[kk * 32 + (c - 64)];
        }
        __syncthreads();
        for (int cc = 0; cc < 48; cc++) {
            int c  = kc * 48 + cc;
            int cx = (c < 64) ? c : (c - 64);
            float b0 = sW[cc * 128 + k];
            float b1 = sW[cc * 128 + 32 + k];
            float b2v = sW[cc * 128 + 64 + k];
            float b3 = sW[cc * 128 + 96 + k];
            #pragma unroll
            for (int r = 0; r < 8; r++) {
                float a = sx[(rg * 8 + r) * 64 + cx];
                acc[r][0] += a * b0;
                acc[r][1] += a * b1;
                acc[r][2] += a * b2v;
                acc[r][3] += a * b3;
            }
        }
    }

    float bi0 = __ldg(&bih[k])      + __ldg(&bhh[k]);
    float bf  = __ldg(&bih[32 + k]) + __ldg(&bhh[32 + k]);
    float bg  = __ldg(&bih[64 + k]) + __ldg(&bhh[64 + k]);
    float bo  = __ldg(&bih[96 + k]) + __ldg(&bhh[96 + k]);
    #pragma unroll
    for (int r = 0; r < 8; r++) {
        int gg = g0 + rg * 8 + r;
        if (gg >= NG) break;
        float i_ = sigm(acc[r][0] + bi0);
        float f_ = sigm(acc[r][1] + bf);
        float gv = tanhf(acc[r][2] + bg);
        float o_ = sigm(acc[r][3] + bo);
        float cn = f_ * g_sc[gg * 32 + k] + i_ * gv;
        g_sc[gg * 32 + k] = cn;
        g_sh[gg * 32 + k] = o_ * tanhf(cn);
    }
}

// ---------------- output head ----------------
__global__ void k_output(const float* __restrict__ W1, const float* __restrict__ b1,
                         const float* __restrict__ W2, const float* __restrict__ b2,
                         float* __restrict__ out) {
    int g = blockIdx.x * blockDim.x + threadIdx.x;
    if (g >= NG) return;
    float emb[64];
    #pragma unroll
    for (int c = 0; c < 32; c++) {
        emb[c]      = g_sh[g * 32 + c];
        emb[32 + c] = g_rr[g * 32 + c];
    }
    float hid[32];
    #pragma unroll
    for (int c = 0; c < 32; c++) {
        float acc = __ldg(&b1[c]);
        #pragma unroll
        for (int d = 0; d < 64; d++) acc += emb[d] * __ldg(&W1[d * 32 + c]);
        hid[c] = fmaxf(acc, 0.0f);
    }
    #pragma unroll
    for (int kk = 0; kk < 3; kk++) {
        float acc = __ldg(&b2[kk]);
        #pragma unroll
        for (int c = 0; c < 32; c++) acc += hid[c] * __ldg(&W2[c * 3 + kk]);
        out[g * 3 + kk] = acc;
    }
}

// ---------------- launch ----------------
extern "C" void kernel_launch(void* const* d_in, const int* in_sizes, int n_in,
                              void* d_out, int out_size) {
    const float* nf     = (const float*)d_in[0];
    const float* ef     = (const float*)d_in[1];
    const float* enc_W  = (const float*)d_in[2];
    const float* enc_b  = (const float*)d_in[3];
    const float* e_W1   = (const float*)d_in[4];
    const float* e_b1   = (const float*)d_in[5];
    const float* e_W2   = (const float*)d_in[6];
    const float* e_b2   = (const float*)d_in[7];
    const float* gWih   = (const float*)d_in[8];
    const float* gWhh   = (const float*)d_in[9];
    const float* gbih   = (const float*)d_in[10];
    const float* gbhh   = (const float*)d_in[11];
    const float* lWih   = (const float*)d_in[12];
    const float* lWhh   = (const float*)d_in[13];
    const float* lbih   = (const float*)d_in[14];
    const float* lbhh   = (const float*)d_in[15];
    const float* oW1    = (const float*)d_in[16];
    const float* ob1    = (const float*)d_in[17];
    const float* oW2    = (const float*)d_in[18];
    const float* ob2    = (const float*)d_in[19];
    const int*   eidx   = (const int*)d_in[20];
    const int*   batch  = (const int*)d_in[21];
    float* out = (float*)d_out;

    k_encode<<<(N_NODES + 255) / 256, 256>>>(nf, enc_W, enc_b);
    k_edgehid<<<(N_EDGES + 255) / 256, 256>>>(ef, e_W1, e_b1);
    k_gemmA<<<dim3(8, (N_EDGES + 127) / 128), 256>>>(e_W2, e_b2);
    k_zero_m<<<(N_NODES * 8 + 255) / 256, 256>>>();

    for (int r = 0; r < 3; r++) {
        k_message<<<(N_EDGES * 32) / 256, 256>>>(eidx);
        k_gru<<<(N_NODES + 255) / 256, 256>>>(gWih, gWhh, gbih, gbhh);
    }

    k_zero_s2s<<<(NG * H + 255) / 256, 256>>>();
    k_offs<<<(N_NODES + 255) / 256, 256>>>(batch);

    for (int s = 0; s < 4; s++) {
        k_attend<<<(NG * 32 + 255) / 256, 256>>>();
        k_lstm<<<(NG + 63) / 64, 256>>>(lWih, lWhh, lbih, lbhh);
    }

    k_output<<<(NG + 255) / 256, 256>>>(oW1, ob1, oW2, ob2, out);
}

// round 6
// speedup vs baseline: 2.6689x; 1.0767x over previous
#include <cuda_runtime.h>
#include <cuda_fp16.h>
#include <math_constants.h>

#define N_NODES 100000
#define N_EDGES 200000
#define NG      2000
#define H       32

typedef unsigned long long ull;

// ---------------- device scratch (alloc-free) ----------------
__device__ float  g_h[N_NODES * H];                 // node hidden     12.8 MB
__device__ float  g_m[N_NODES * H];                 // aggregated msgs 12.8 MB
__device__ __half g_rh[(size_t)N_EDGES * 64];       // edge hidden fp16 25.6 MB
__device__ __half g_W2h[1024 * 64];                 // W2 fp16 transposed [n][k], 128 KB
__device__ float  g_sh[NG * H];                     // set2set h
__device__ float  g_sc[NG * H];                     // set2set c
__device__ float  g_rr[NG * H];                     // readout r
__device__ int    g_offs[NG + 1];                   // graph segment offsets

// ---------------- helpers ----------------
__device__ __forceinline__ ull pk2(float x) {
    ull r; asm("mov.b64 %0, {%1, %1};" : "=l"(r) : "f"(x)); return r;
}
__device__ __forceinline__ ull pkab(float lo, float hi) {
    ull r; asm("mov.b64 %0, {%1, %2};" : "=l"(r) : "f"(lo), "f"(hi)); return r;
}
__device__ __forceinline__ ull fma2(ull a, ull b, ull c) {
    ull d; asm("fma.rn.f32x2 %0, %1, %2, %3;" : "=l"(d) : "l"(a), "l"(b), "l"(c)); return d;
}
__device__ __forceinline__ void unpk2(ull v, float& lo, float& hi) {
    asm("mov.b64 {%0, %1}, %2;" : "=f"(lo), "=f"(hi) : "l"(v));
}
__device__ __forceinline__ float warpMax(float v) {
    #pragma unroll
    for (int o = 16; o > 0; o >>= 1) v = fmaxf(v, __shfl_xor_sync(0xffffffffu, v, o));
    return v;
}
__device__ __forceinline__ float warpSum(float v) {
    #pragma unroll
    for (int o = 16; o > 0; o >>= 1) v += __shfl_xor_sync(0xffffffffu, v, o);
    return v;
}
__device__ __forceinline__ float sigm(float x) { return 1.0f / (1.0f + expf(-x)); }

// ---------------- zero kernels ----------------
__global__ void k_zero_m() {
    int i = blockIdx.x * blockDim.x + threadIdx.x;
    if (i < N_NODES * 8) ((float4*)g_m)[i] = make_float4(0.f, 0.f, 0.f, 0.f);
}
__global__ void k_zero_s2s() {
    int i = blockIdx.x * blockDim.x + threadIdx.x;
    if (i < NG * H) { g_sh[i] = 0.0f; g_sc[i] = 0.0f; g_rr[i] = 0.0f; }
}

// ---------------- W2 pack: g_W2h[n][k] = fp16(W2[k][n]) ----------------
__global__ void k_packW2(const float* __restrict__ W2) {
    int i = blockIdx.x * blockDim.x + threadIdx.x;
    if (i >= 64 * 1024) return;
    int k = i >> 10, n = i & 1023;
    g_W2h[n * 64 + k] = __float2half_rn(W2[i]);
}

// ---------------- encoder: h = nf @ enc_W + enc_b ----------------
__global__ void k_encode(const float* __restrict__ nf, const float* __restrict__ W,
                         const float* __restrict__ b) {
    __shared__ float sW[16 * 32];
    __shared__ float sb[32];
    int t = threadIdx.x;
    for (int i = t; i < 512; i += 256) sW[i] = W[i];
    if (t < 32) sb[t] = b[t];
    __syncthreads();
    int n = blockIdx.x * blockDim.x + t;
    if (n >= N_NODES) return;
    float x[16];
    const float4* p = (const float4*)(nf + (long long)n * 16);
    #pragma unroll
    for (int q = 0; q < 4; q++) {
        float4 v = p[q];
        x[q*4+0] = v.x; x[q*4+1] = v.y; x[q*4+2] = v.z; x[q*4+3] = v.w;
    }
    #pragma unroll
    for (int c = 0; c < 32; c++) {
        float acc = sb[c];
        #pragma unroll
        for (int d = 0; d < 16; d++) acc += x[d] * sW[d * 32 + c];
        g_h[n * 32 + c] = acc;
    }
}

// ---------------- edge hidden: rh = fp16(relu(ef @ e_W1 + e_b1)) ----------------
__global__ void k_edgehid(const float* __restrict__ ef, const float* __restrict__ W,
                          const float* __restrict__ b) {
    __shared__ float sW[8 * 64];
    __shared__ float sb[64];
    int t = threadIdx.x;
    for (int i = t; i < 512; i += 256) sW[i] = W[i];
    if (t < 64) sb[t] = b[t];
    __syncthreads();
    int e = blockIdx.x * blockDim.x + t;
    if (e >= N_EDGES) return;
    float x[8];
    const float4* p = (const float4*)(ef + (long long)e * 8);
    float4 v0 = p[0], v1 = p[1];
    x[0]=v0.x; x[1]=v0.y; x[2]=v0.z; x[3]=v0.w;
    x[4]=v1.x; x[5]=v1.y; x[6]=v1.z; x[7]=v1.w;
    float o[64];
    #pragma unroll
    for (int c = 0; c < 64; c++) {
        float acc = sb[c];
        #pragma unroll
        for (int d = 0; d < 8; d++) acc += x[d] * sW[d * 64 + c];
        o[c] = fmaxf(acc, 0.0f);
    }
    __half2* dst = (__half2*)&g_rh[(size_t)e * 64];
    #pragma unroll
    for (int c2 = 0; c2 < 32; c2++)
        dst[c2] = __floats2half2_rn(o[2 * c2], o[2 * c2 + 1]);
}

// ---------------- FUSED message pass: m[tgt] += (rh[e] @ W2 + b2) @ h[src] ------
// Per block: 128 edges. A tile is computed by HMMA per 128-col chunk and consumed
// immediately from registers; A never hits DRAM.
// Warp layout per chunk: warpM=(wid&1)*64, warpN=(wid>>1)*32 -> each warp's 32
// cols are one output index i = 4*chunk + (wid>>1), all 32 j's.
#define ROWP 72
__global__ void __launch_bounds__(256) k_msg_fused(const int* __restrict__ ei,
                                                   const float* __restrict__ b2) {
    __shared__ __half Rs[128 * ROWP];    // rh tile [m][k]   18432 B
    __shared__ __half Wt[128 * ROWP];    // W2 chunk [n][k]  18432 B
    __shared__ __half Hs[128 * 34];      // gathered h fp16   8704 B
    __shared__ float  b2s[128];          //                    512 B
    __shared__ int    sTgt[128];         //                    512 B
    int t    = threadIdx.x;
    int lane = t & 31;
    int wid  = t >> 5;
    int e0   = blockIdx.x * 128;

    // load rh tile [128 x 64] fp16
    #pragma unroll
    for (int i = 0; i < 4; i++) {
        int g   = t + 256 * i;
        int row = g >> 3;
        int kg  = g & 7;
        uint4 v = make_uint4(0u, 0u, 0u, 0u);
        int e = e0 + row;
        if (e < N_EDGES) v = *(const uint4*)&g_rh[(size_t)e * 64 + kg * 8];
        *(uint4*)&Rs[row * ROWP + kg * 8] = v;
    }
    // gather h[src] -> Hs fp16 [row][34 pad]; load tgt
    {
        int row = t >> 1, hf = t & 1;
        int e = e0 + row;
        int src = 0;
        bool ok = e < N_EDGES;
        if (ok) {
            src = ei[e];
            if (hf == 0) sTgt[row] = ei[N_EDGES + e];
        }
        const float4* hp = (const float4*)&g_h[src * 32 + hf * 16];
        #pragma unroll
        for (int qq = 0; qq < 4; qq++) {
            float4 v = ok ? hp[qq] : make_float4(0.f, 0.f, 0.f, 0.f);
            __half2* d = (__half2*)&Hs[row * 34 + hf * 16 + qq * 4];
            d[0] = __floats2half2_rn(v.x, v.y);
            d[1] = __floats2half2_rn(v.z, v.w);
        }
    }

    int warpM = (wid & 1) * 64;
    int warpN = (wid >> 1) * 32;
    int aRow  = warpM + (lane & 15);
    int aColB = (lane >> 4) << 3;
    int bRow  = warpN + (lane & 7) + ((lane >> 4) << 3);
    int bColB = ((lane >> 3) & 1) << 3;

    #pragma unroll 1
    for (int c = 0; c < 8; c++) {
        __syncthreads();   // prior chunk done with Wt; first iter: Rs/Hs ready
        // load W2 chunk [128 n x 64 k] fp16 (prepacked transposed, L2-resident)
        #pragma unroll
        for (int i = 0; i < 4; i++) {
            int g   = t + 256 * i;
            int row = g >> 3;
            int kg  = g & 7;
            *(uint4*)&Wt[row * ROWP + kg * 8] =
                *(const uint4*)&g_W2h[(size_t)(c * 128 + row) * 64 + kg * 8];
        }
        if (t < 128) b2s[t] = b2[c * 128 + t];
        __syncthreads();

        float acc[4][4][4];
        #pragma unroll
        for (int mt = 0; mt < 4; mt++)
            #pragma unroll
            for (int nt = 0; nt < 4; nt++)
                #pragma unroll
                for (int q = 0; q < 4; q++) acc[mt][nt][q] = 0.0f;

        #pragma unroll
        for (int ks = 0; ks < 4; ks++) {
            int k0 = ks * 16;
            unsigned a[4][4];
            #pragma unroll
            for (int mt = 0; mt < 4; mt++) {
                unsigned addr = (unsigned)__cvta_generic_to_shared(
                    &Rs[(aRow + mt * 16) * ROWP + k0 + aColB]);
                asm volatile("ldmatrix.sync.aligned.m8n8.x4.shared.b16 {%0,%1,%2,%3}, [%4];"
                             : "=r"(a[mt][0]), "=r"(a[mt][1]), "=r"(a[mt][2]), "=r"(a[mt][3])
                             : "r"(addr));
            }
            unsigned bf[4][2];
            #pragma unroll
            for (int p = 0; p < 2; p++) {
                unsigned addr = (unsigned)__cvta_generic_to_shared(
                    &Wt[(bRow + p * 16) * ROWP + k0 + bColB]);
                asm volatile("ldmatrix.sync.aligned.m8n8.x4.shared.b16 {%0,%1,%2,%3}, [%4];"
                             : "=r"(bf[2*p][0]), "=r"(bf[2*p][1]),
                               "=r"(bf[2*p+1][0]), "=r"(bf[2*p+1][1])
                             : "r"(addr));
            }
            #pragma unroll
            for (int mt = 0; mt < 4; mt++)
                #pragma unroll
                for (int nt = 0; nt < 4; nt++) {
                    asm volatile(
                        "mma.sync.aligned.m16n8k16.row.col.f32.f16.f16.f32 "
                        "{%0,%1,%2,%3}, {%4,%5,%6,%7}, {%8,%9}, {%0,%1,%2,%3};"
                        : "+f"(acc[mt][nt][0]), "+f"(acc[mt][nt][1]),
                          "+f"(acc[mt][nt][2]), "+f"(acc[mt][nt][3])
                        : "r"(a[mt][0]), "r"(a[mt][1]), "r"(a[mt][2]), "r"(a[mt][3]),
                          "r"(bf[nt][0]), "r"(bf[nt][1]));
                }
        }

        // bias (A includes b2)
        #pragma unroll
        for (int nt = 0; nt < 4; nt++) {
            float2 bb = *(const float2*)&b2s[warpN + nt * 8 + (lane & 3) * 2];
            #pragma unroll
            for (int mt = 0; mt < 4; mt++) {
                acc[mt][nt][0] += bb.x; acc[mt][nt][1] += bb.y;
                acc[mt][nt][2] += bb.x; acc[mt][nt][3] += bb.y;
            }
        }

        // matvec over j within the warp + scatter
        int i_out = 4 * c + (wid >> 1);
        const __half2* Hs2 = (const __half2*)Hs;
        #pragma unroll
        for (int mt = 0; mt < 4; mt++) {
            #pragma unroll
            for (int qh = 0; qh < 2; qh++) {
                int rowl = warpM + mt * 16 + (lane >> 2) + 8 * qh;
                float partial = 0.0f;
                #pragma unroll
                for (int nt = 0; nt < 4; nt++) {
                    float2 hf2 = __half22float2(Hs2[rowl * 17 + nt * 4 + (lane & 3)]);
                    partial += acc[mt][nt][2 * qh + 0] * hf2.x;
                    partial += acc[mt][nt][2 * qh + 1] * hf2.y;
                }
                partial += __shfl_xor_sync(0xffffffffu, partial, 1);
                partial += __shfl_xor_sync(0xffffffffu, partial, 2);
                if ((lane & 3) == 0 && (e0 + rowl) < N_EDGES)
                    atomicAdd(&g_m[sTgt[rowl] * 32 + i_out], partial);
            }
        }
    }
}

// ---------------- GRU cell (f32x2 k-pairs); zeroes g_m for next round --------
__global__ void __launch_bounds__(256) k_gru(const float* __restrict__ Wih,
                                             const float* __restrict__ Whh,
                                             const float* __restrict__ bih,
                                             const float* __restrict__ bhh) {
    __shared__ ull sWi2[3 * 16 * 32];
    __shared__ ull sWh2[3 * 16 * 32];
    __shared__ float sbi[96];
    __shared__ float sbh[96];
    int t = threadIdx.x;
    for (int i = t; i < 1536; i += 256) {
        int g  = i >> 9;
        int k2 = (i >> 5) & 15;
        int c  = i & 31;
        int k  = g * 32 + 2 * k2;
        sWi2[i] = pkab(Wih[k * 32 + c], Wih[(k + 1) * 32 + c]);
        sWh2[i] = pkab(Whh[k * 32 + c], Whh[(k + 1) * 32 + c]);
    }
    if (t < 96) { sbi[t] = bih[t]; sbh[t] = bhh[t]; }
    __syncthreads();
    int n = blockIdx.x * blockDim.x + t;
    if (n >= N_NODES) return;

    float mv[32], hv[32];
    const float4* mp = (const float4*)&g_m[n * 32];
    const float4* hp = (const float4*)&g_h[n * 32];
    #pragma unroll
    for (int q = 0; q < 8; q++) {
        float4 a = mp[q]; mv[q*4]=a.x; mv[q*4+1]=a.y; mv[q*4+2]=a.z; mv[q*4+3]=a.w;
        float4 b = hp[q]; hv[q*4]=b.x; hv[q*4+1]=b.y; hv[q*4+2]=b.z; hv[q*4+3]=b.w;
    }
    float4* mz = (float4*)&g_m[n * 32];
    #pragma unroll
    for (int q = 0; q < 8; q++) mz[q] = make_float4(0.f, 0.f, 0.f, 0.f);

    #pragma unroll 1
    for (int k2 = 0; k2 < 16; k2++) {
        int k = 2 * k2;
        ull accr = pkab(sbi[k] + sbh[k], sbi[k + 1] + sbh[k + 1]);
        ull accz = pkab(sbi[32 + k] + sbh[32 + k], sbi[33 + k] + sbh[33 + k]);
        ull accn = pkab(sbi[64 + k], sbi[65 + k]);
        ull acch = pkab(sbh[64 + k], sbh[65 + k]);
        const ull* wir = &sWi2[(0 * 16 + k2) * 32];
        const ull* wiz = &sWi2[(1 * 16 + k2) * 32];
        const ull* win = &sWi2[(2 * 16 + k2) * 32];
        const ull* whr = &sWh2[(0 * 16 + k2) * 32];
        const ull* whz = &sWh2[(1 * 16 + k2) * 32];
        const ull* whn = &sWh2[(2 * 16 + k2) * 32];
        #pragma unroll
        for (int c = 0; c < 32; c++) {
            ull pm = pk2(mv[c]);
            ull ph = pk2(hv[c]);
            accr = fma2(pm, wir[c], accr);
            accr = fma2(ph, whr[c], accr);
            accz = fma2(pm, wiz[c], accz);
            accz = fma2(ph, whz[c], accz);
            accn = fma2(pm, win[c], accn);
            acch = fma2(ph, whn[c], acch);
        }
        float rlo, rhi, zlo, zhi, nlo, nhi, hlo, hhi;
        unpk2(accr, rlo, rhi);
        unpk2(accz, zlo, zhi);
        unpk2(accn, nlo, nhi);
        unpk2(acch, hlo, hhi);
        float r0 = sigm(rlo), z0 = sigm(zlo);
        float n0 = tanhf(nlo + r0 * hlo);
        float r1 = sigm(rhi), z1 = sigm(zhi);
        float n1 = tanhf(nhi + r1 * hhi);
        float2 hnew;
        hnew.x = (1.0f - z0) * n0 + z0 * hv[k];
        hnew.y = (1.0f - z1) * n1 + z1 * hv[k + 1];
        *(float2*)&g_h[n * 32 + k] = hnew;
    }
}

// ---------------- graph segment offsets (batch_indices sorted) ----------------
__global__ void k_offs(const int* __restrict__ batch) {
    int n = blockIdx.x * blockDim.x + threadIdx.x;
    if (n >= N_NODES) return;
    int b = batch[n];
    int prev = (n == 0) ? -1 : batch[n - 1];
    for (int g = prev + 1; g <= b; g++) g_offs[g] = n;
    if (n == N_NODES - 1)
        for (int g = b + 1; g <= NG; g++) g_offs[g] = N_NODES;
}

// ---------------- Set2Set attention + readout (online softmax, warp/graph) ----
__global__ void __launch_bounds__(256) k_attend() {
    int lane = threadIdx.x & 31;
    int g = (blockIdx.x * blockDim.x + threadIdx.x) >> 5;
    if (g >= NG) return;
    int s = g_offs[g], tEnd = g_offs[g + 1];
    float q = g_sh[g * 32 + lane];
    float maxv = -CUDART_INF_F, denom = 0.0f, racc = 0.0f;

    for (int base = s; base < tEnd; base += 32) {
        int n = base + lane;
        bool act = n < tEnd;
        int nn = act ? n : s;
        float rv[32];
        const float4* hp4 = (const float4*)&g_h[nn * 32];
        #pragma unroll
        for (int q4 = 0; q4 < 8; q4++) {
            float4 v = hp4[q4];
            rv[q4*4] = v.x; rv[q4*4+1] = v.y; rv[q4*4+2] = v.z; rv[q4*4+3] = v.w;
        }
        float ev = 0.0f;
        #pragma unroll
        for (int j = 0; j < 32; j++)
            ev += rv[j] * __shfl_sync(0xffffffffu, q, j);
        float e_n = act ? ev : -CUDART_INF_F;
        float cm = warpMax(e_n);
        float nm = fmaxf(maxv, cm);
        float scale = (maxv == -CUDART_INF_F) ? 0.0f : expf(maxv - nm);
        float p = act ? expf(e_n - nm) : 0.0f;
        float ps = warpSum(p);
        denom = denom * scale + ps;
        racc *= scale;
        maxv = nm;
        int cnt = min(32, tEnd - base);
        for (int n2 = 0; n2 < cnt; n2++) {
            float pn = __shfl_sync(0xffffffffu, p, n2);
            racc += pn * g_h[(base + n2) * 32 + lane];
        }
    }
    g_rr[g * 32 + lane] = (denom > 0.0f) ? (racc / denom) : 0.0f;
}

// ---------------- Set2Set LSTM step (fused mini-GEMM, 64 graphs/block) --------
__global__ void __launch_bounds__(256) k_lstm(const float* __restrict__ Wih,
                                              const float* __restrict__ Whh,
                                              const float* __restrict__ bih,
                                              const float* __restrict__ bhh) {
    __shared__ float sx[64 * 64];
    __shared__ float sW[48 * 128];
    int t  = threadIdx.x;
    int g0 = blockIdx.x * 64;
    int k  = t & 31;
    int rg = t >> 5;

    for (int i = t; i < 64 * 64; i += 256) {
        int g = i >> 6, c = i & 63;
        int gg = g0 + g;
        float v = 0.0f;
        if (gg < NG) v = (c < 32) ? g_sh[gg * 32 + c] : g_rr[gg * 32 + (c - 32)];
        sx[i] = v;
    }

    float acc[8][4];
    #pragma unroll
    for (int r = 0; r < 8; r++)
        #pragma unroll
        for (int j = 0; j < 4; j++) acc[r][j] = 0.0f;

    #pragma unroll 1
    for (int kc = 0; kc < 2; kc++) {
        __syncthreads();
        for (int i = t; i < 48 * 128; i += 256) {
            int c  = kc * 48 + (i >> 7);
            int kk = i & 127;
            sW[i] = (c < 64) ? Wih[kk * 64 + c] : Whh[kk * 32 + (c - 64)];
        }
        __syncthreads();
        for (int cc = 0; cc < 48; cc++) {
            int c  = kc * 48 + cc;
            int cx = (c < 64) ? c : (c - 64);
            float b0 = sW[cc * 128 + k];
            float b1 = sW[cc * 128 + 32 + k];
            float b2v = sW[cc * 128 + 64 + k];
            float b3 = sW[cc * 128 + 96 + k];
            #pragma unroll
            for (int r = 0; r < 8; r++) {
                float a = sx[(rg * 8 + r) * 64 + cx];
                acc[r][0] += a * b0;
                acc[r][1] += a * b1;
                acc[r][2] += a * b2v;
                acc[r][3] += a * b3;
            }
        }
    }

    float bi0 = __ldg(&bih[k])      + __ldg(&bhh[k]);
    float bf  = __ldg(&bih[32 + k]) + __ldg(&bhh[32 + k]);
    float bg  = __ldg(&bih[64 + k]) + __ldg(&bhh[64 + k]);
    float bo  = __ldg(&bih[96 + k]) + __ldg(&bhh[96 + k]);
    #pragma unroll
    for (int r = 0; r < 8; r++) {
        int gg = g0 + rg * 8 + r;
        if (gg >= NG) break;
        float i_ = sigm(acc[r][0] + bi0);
        float f_ = sigm(acc[r][1] + bf);
        float gv = tanhf(acc[r][2] + bg);
        float o_ = sigm(acc[r][3] + bo);
        float cn = f_ * g_sc[gg * 32 + k] + i_ * gv;
        g_sc[gg * 32 + k] = cn;
        g_sh[gg * 32 + k] = o_ * tanhf(cn);
    }
}

// ---------------- output head ----------------
__global__ void k_output(const float* __restrict__ W1, const float* __restrict__ b1,
                         const float* __restrict__ W2, const float* __restrict__ b2,
                         float* __restrict__ out) {
    int g = blockIdx.x * blockDim.x + threadIdx.x;
    if (g >= NG) return;
    float emb[64];
    #pragma unroll
    for (int c = 0; c < 32; c++) {
        emb[c]      = g_sh[g * 32 + c];
        emb[32 + c] = g_rr[g * 32 + c];
    }
    float hid[32];
    #pragma unroll
    for (int c = 0; c < 32; c++) {
        float acc = __ldg(&b1[c]);
        #pragma unroll
        for (int d = 0; d < 64; d++) acc += emb[d] * __ldg(&W1[d * 32 + c]);
        hid[c] = fmaxf(acc, 0.0f);
    }
    #pragma unroll
    for (int kk = 0; kk < 3; kk++) {
        float acc = __ldg(&b2[kk]);
        #pragma unroll
        for (int c = 0; c < 32; c++) acc += hid[c] * __ldg(&W2[c * 3 + kk]);
        out[g * 3 + kk] = acc;
    }
}

// ---------------- launch ----------------
extern "C" void kernel_launch(void* const* d_in, const int* in_sizes, int n_in,
                              void* d_out, int out_size) {
    const float* nf     = (const float*)d_in[0];
    const float* ef     = (const float*)d_in[1];
    const float* enc_W  = (const float*)d_in[2];
    const float* enc_b  = (const float*)d_in[3];
    const float* e_W1   = (const float*)d_in[4];
    const float* e_b1   = (const float*)d_in[5];
    const float* e_W2   = (const float*)d_in[6];
    const float* e_b2   = (const float*)d_in[7];
    const float* gWih   = (const float*)d_in[8];
    const float* gWhh   = (const float*)d_in[9];
    const float* gbih   = (const float*)d_in[10];
    const float* gbhh   = (const float*)d_in[11];
    const float* lWih   = (const float*)d_in[12];
    const float* lWhh   = (const float*)d_in[13];
    const float* lbih   = (const float*)d_in[14];
    const float* lbhh   = (const float*)d_in[15];
    const float* oW1    = (const float*)d_in[16];
    const float* ob1    = (const float*)d_in[17];
    const float* oW2    = (const float*)d_in[18];
    const float* ob2    = (const float*)d_in[19];
    const int*   eidx   = (const int*)d_in[20];
    const int*   batch  = (const int*)d_in[21];
    float* out = (float*)d_out;

    k_encode<<<(N_NODES + 255) / 256, 256>>>(nf, enc_W, enc_b);
    k_edgehid<<<(N_EDGES + 255) / 256, 256>>>(ef, e_W1, e_b1);
    k_packW2<<<(64 * 1024 + 255) / 256, 256>>>(e_W2);
    k_zero_m<<<(N_NODES * 8 + 255) / 256, 256>>>();

    for (int r = 0; r < 3; r++) {
        k_msg_fused<<<(N_EDGES + 127) / 128, 256>>>(eidx, e_b2);
        k_gru<<<(N_NODES + 255) / 256, 256>>>(gWih, gWhh, gbih, gbhh);
    }

    k_zero_s2s<<<(NG * H + 255) / 256, 256>>>();
    k_offs<<<(N_NODES + 255) / 256, 256>>>(batch);

    for (int s = 0; s < 4; s++) {
        k_attend<<<(NG * 32 + 255) / 256, 256>>>();
        k_lstm<<<(NG + 63) / 64, 256>>>(lWih, lWhh, lbih, lbhh);
    }

    k_output<<<(NG + 255) / 256, 256>>>(oW1, ob1, oW2, ob2, out);
}

// round 7
// speedup vs baseline: 2.7326x; 1.0239x over previous
#include <cuda_runtime.h>
#include <cuda_fp16.h>
#include <math_constants.h>

#define N_NODES 100000
#define N_EDGES 200000
#define NG      2000
#define H       32

typedef unsigned long long ull;

// ---------------- device scratch (alloc-free) ----------------
__device__ float  g_h[N_NODES * H];                 // node hidden fp32  12.8 MB
__device__ __half g_hh[N_NODES * H];                // node hidden fp16   6.4 MB
__device__ float  g_m[N_NODES * H];                 // aggregated msgs   12.8 MB
__device__ __half g_rh[(size_t)N_EDGES * 64];       // edge hidden fp16  25.6 MB
__device__ __half g_W2h[1024 * 64];                 // W2 fp16 transposed [n][k], 128 KB
__device__ float  g_sh[NG * H];                     // set2set h
__device__ float  g_sc[NG * H];                     // set2set c
__device__ float  g_rr[NG * H];                     // readout r
__device__ int    g_offs[NG + 1];                   // graph segment offsets

// ---------------- helpers ----------------
__device__ __forceinline__ ull pk2(float x) {
    ull r; asm("mov.b64 %0, {%1, %1};" : "=l"(r) : "f"(x)); return r;
}
__device__ __forceinline__ ull pkab(float lo, float hi) {
    ull r; asm("mov.b64 %0, {%1, %2};" : "=l"(r) : "f"(lo), "f"(hi)); return r;
}
__device__ __forceinline__ ull fma2(ull a, ull b, ull c) {
    ull d; asm("fma.rn.f32x2 %0, %1, %2, %3;" : "=l"(d) : "l"(a), "l"(b), "l"(c)); return d;
}
__device__ __forceinline__ void unpk2(ull v, float& lo, float& hi) {
    asm("mov.b64 {%0, %1}, %2;" : "=f"(lo), "=f"(hi) : "l"(v));
}
__device__ __forceinline__ float warpMax(float v) {
    #pragma unroll
    for (int o = 16; o > 0; o >>= 1) v = fmaxf(v, __shfl_xor_sync(0xffffffffu, v, o));
    return v;
}
__device__ __forceinline__ float warpSum(float v) {
    #pragma unroll
    for (int o = 16; o > 0; o >>= 1) v += __shfl_xor_sync(0xffffffffu, v, o);
    return v;
}
__device__ __forceinline__ float sigm(float x) { return 1.0f / (1.0f + expf(-x)); }

// ---------------- zero (set2set state only) ----------------
__global__ void k_zero_s2s() {
    int i = blockIdx.x * blockDim.x + threadIdx.x;
    if (i < NG * H) { g_sh[i] = 0.0f; g_sc[i] = 0.0f; g_rr[i] = 0.0f; }
}

// ---------------- W2 pack: g_W2h[n][k] = fp16(W2[k][n]) ----------------
__global__ void k_packW2(const float* __restrict__ W2) {
    int i = blockIdx.x * blockDim.x + threadIdx.x;
    if (i >= 64 * 1024) return;
    int k = i >> 10, n = i & 1023;
    g_W2h[n * 64 + k] = __float2half_rn(W2[i]);
}

// ---------------- encoder: h = nf @ enc_W + enc_b; writes fp16 mirror; zeros m
__global__ void k_encode(const float* __restrict__ nf, const float* __restrict__ W,
                         const float* __restrict__ b) {
    __shared__ float sW[16 * 32];
    __shared__ float sb[32];
    int t = threadIdx.x;
    for (int i = t; i < 512; i += 256) sW[i] = W[i];
    if (t < 32) sb[t] = b[t];
    __syncthreads();
    int n = blockIdx.x * blockDim.x + t;
    if (n >= N_NODES) return;
    float x[16];
    const float4* p = (const float4*)(nf + (long long)n * 16);
    #pragma unroll
    for (int q = 0; q < 4; q++) {
        float4 v = p[q];
        x[q*4+0] = v.x; x[q*4+1] = v.y; x[q*4+2] = v.z; x[q*4+3] = v.w;
    }
    float hv[32];
    #pragma unroll
    for (int c = 0; c < 32; c++) {
        float acc = sb[c];
        #pragma unroll
        for (int d = 0; d < 16; d++) acc += x[d] * sW[d * 32 + c];
        hv[c] = acc;
    }
    float4* hp = (float4*)&g_h[n * 32];
    float4* mz = (float4*)&g_m[n * 32];
    __half2* hh = (__half2*)&g_hh[n * 32];
    #pragma unroll
    for (int q = 0; q < 8; q++) {
        hp[q] = make_float4(hv[q*4], hv[q*4+1], hv[q*4+2], hv[q*4+3]);
        mz[q] = make_float4(0.f, 0.f, 0.f, 0.f);
    }
    #pragma unroll
    for (int c2 = 0; c2 < 16; c2++)
        hh[c2] = __floats2half2_rn(hv[2*c2], hv[2*c2+1]);
}

// ---------------- edge hidden: rh = fp16(relu(ef @ e_W1 + e_b1)) ----------------
__global__ void k_edgehid(const float* __restrict__ ef, const float* __restrict__ W,
                          const float* __restrict__ b) {
    __shared__ float sW[8 * 64];
    __shared__ float sb[64];
    int t = threadIdx.x;
    for (int i = t; i < 512; i += 256) sW[i] = W[i];
    if (t < 64) sb[t] = b[t];
    __syncthreads();
    int e = blockIdx.x * blockDim.x + t;
    if (e >= N_EDGES) return;
    float x[8];
    const float4* p = (const float4*)(ef + (long long)e * 8);
    float4 v0 = p[0], v1 = p[1];
    x[0]=v0.x; x[1]=v0.y; x[2]=v0.z; x[3]=v0.w;
    x[4]=v1.x; x[5]=v1.y; x[6]=v1.z; x[7]=v1.w;
    float o[64];
    #pragma unroll
    for (int c = 0; c < 64; c++) {
        float acc = sb[c];
        #pragma unroll
        for (int d = 0; d < 8; d++) acc += x[d] * sW[d * 64 + c];
        o[c] = fmaxf(acc, 0.0f);
    }
    __half2* dst = (__half2*)&g_rh[(size_t)e * 64];
    #pragma unroll
    for (int c2 = 0; c2 < 32; c2++)
        dst[c2] = __floats2half2_rn(o[2 * c2], o[2 * c2 + 1]);
}

// ---------------- FUSED message pass: m[tgt] += (rh[e] @ W2 + b2) @ h[src] ------
// Per block: 128 edges. A tile computed per 128-col chunk via HMMA, consumed
// from registers; A never hits DRAM. Hs stride 40 halves (80 B): 16B-aligned
// uint4 fills, conflict-free epilogue reads (20q mod 32 distinct).
#define ROWP 72
#define HSTR 40
__global__ void __launch_bounds__(256) k_msg_fused(const int* __restrict__ ei,
                                                   const float* __restrict__ b2) {
    __shared__ __half Rs[128 * ROWP];    // rh tile [m][k]   18432 B
    __shared__ __half Wt[128 * ROWP];    // W2 chunk [n][k]  18432 B
    __shared__ __half Hs[128 * HSTR];    // gathered h fp16  10240 B
    __shared__ float  b2s[128];          //                    512 B
    __shared__ int    sTgt[128];         //                    512 B
    int t    = threadIdx.x;
    int lane = t & 31;
    int wid  = t >> 5;
    int e0   = blockIdx.x * 128;

    // load rh tile [128 x 64] fp16
    #pragma unroll
    for (int i = 0; i < 4; i++) {
        int g   = t + 256 * i;
        int row = g >> 3;
        int kg  = g & 7;
        uint4 v = make_uint4(0u, 0u, 0u, 0u);
        int e = e0 + row;
        if (e < N_EDGES) v = *(const uint4*)&g_rh[(size_t)e * 64 + kg * 8];
        *(uint4*)&Rs[row * ROWP + kg * 8] = v;
    }
    // gather h[src] fp16 -> Hs; load tgt
    {
        int row = t >> 1, hf = t & 1;
        int e = e0 + row;
        bool ok = e < N_EDGES;
        int src = 0;
        if (ok) {
            src = ei[e];
            if (hf == 0) sTgt[row] = ei[N_EDGES + e];
        }
        const uint4* hp = (const uint4*)&g_hh[src * 32 + hf * 16];
        #pragma unroll
        for (int qq = 0; qq < 2; qq++) {
            uint4 v = ok ? hp[qq] : make_uint4(0u, 0u, 0u, 0u);
            *(uint4*)&Hs[row * HSTR + hf * 16 + qq * 8] = v;
        }
    }

    int warpM = (wid & 1) * 64;
    int warpN = (wid >> 1) * 32;
    int aRow  = warpM + (lane & 15);
    int aColB = (lane >> 4) << 3;
    int bRow  = warpN + (lane & 7) + ((lane >> 4) << 3);
    int bColB = ((lane >> 3) & 1) << 3;

    #pragma unroll 1
    for (int c = 0; c < 8; c++) {
        __syncthreads();
        // load W2 chunk [128 n x 64 k] fp16 (prepacked transposed, L2-resident)
        #pragma unroll
        for (int i = 0; i < 4; i++) {
            int g   = t + 256 * i;
            int row = g >> 3;
            int kg  = g & 7;
            *(uint4*)&Wt[row * ROWP + kg * 8] =
                *(const uint4*)&g_W2h[(size_t)(c * 128 + row) * 64 + kg * 8];
        }
        if (t < 128) b2s[t] = b2[c * 128 + t];
        __syncthreads();

        float acc[4][4][4];
        #pragma unroll
        for (int mt = 0; mt < 4; mt++)
            #pragma unroll
            for (int nt = 0; nt < 4; nt++)
                #pragma unroll
                for (int q = 0; q < 4; q++) acc[mt][nt][q] = 0.0f;

        #pragma unroll
        for (int ks = 0; ks < 4; ks++) {
            int k0 = ks * 16;
            unsigned a[4][4];
            #pragma unroll
            for (int mt = 0; mt < 4; mt++) {
                unsigned addr = (unsigned)__cvta_generic_to_shared(
                    &Rs[(aRow + mt * 16) * ROWP + k0 + aColB]);
                asm volatile("ldmatrix.sync.aligned.m8n8.x4.shared.b16 {%0,%1,%2,%3}, [%4];"
                             : "=r"(a[mt][0]), "=r"(a[mt][1]), "=r"(a[mt][2]), "=r"(a[mt][3])
                             : "r"(addr));
            }
            unsigned bf[4][2];
            #pragma unroll
            for (int p = 0; p < 2; p++) {
                unsigned addr = (unsigned)__cvta_generic_to_shared(
                    &Wt[(bRow + p * 16) * ROWP + k0 + bColB]);
                asm volatile("ldmatrix.sync.aligned.m8n8.x4.shared.b16 {%0,%1,%2,%3}, [%4];"
                             : "=r"(bf[2*p][0]), "=r"(bf[2*p][1]),
                               "=r"(bf[2*p+1][0]), "=r"(bf[2*p+1][1])
                             : "r"(addr));
            }
            #pragma unroll
            for (int mt = 0; mt < 4; mt++)
                #pragma unroll
                for (int nt = 0; nt < 4; nt++) {
                    asm volatile(
                        "mma.sync.aligned.m16n8k16.row.col.f32.f16.f16.f32 "
                        "{%0,%1,%2,%3}, {%4,%5,%6,%7}, {%8,%9}, {%0,%1,%2,%3};"
                        : "+f"(acc[mt][nt][0]), "+f"(acc[mt][nt][1]),
                          "+f"(acc[mt][nt][2]), "+f"(acc[mt][nt][3])
                        : "r"(a[mt][0]), "r"(a[mt][1]), "r"(a[mt][2]), "r"(a[mt][3]),
                          "r"(bf[nt][0]), "r"(bf[nt][1]));
                }
        }

        // bias
        #pragma unroll
        for (int nt = 0; nt < 4; nt++) {
            float2 bb = *(const float2*)&b2s[warpN + nt * 8 + (lane & 3) * 2];
            #pragma unroll
            for (int mt = 0; mt < 4; mt++) {
                acc[mt][nt][0] += bb.x; acc[mt][nt][1] += bb.y;
                acc[mt][nt][2] += bb.x; acc[mt][nt][3] += bb.y;
            }
        }

        // matvec over j within the warp + scatter
        int i_out = 4 * c + (wid >> 1);
        const __half2* Hs2 = (const __half2*)Hs;
        #pragma unroll
        for (int mt = 0; mt < 4; mt++) {
            #pragma unroll
            for (int qh = 0; qh < 2; qh++) {
                int rowl = warpM + mt * 16 + (lane >> 2) + 8 * qh;
                float partial = 0.0f;
                #pragma unroll
                for (int nt = 0; nt < 4; nt++) {
                    float2 hf2 = __half22float2(Hs2[rowl * (HSTR/2) + nt * 4 + (lane & 3)]);
                    partial += acc[mt][nt][2 * qh + 0] * hf2.x;
                    partial += acc[mt][nt][2 * qh + 1] * hf2.y;
                }
                partial += __shfl_xor_sync(0xffffffffu, partial, 1);
                partial += __shfl_xor_sync(0xffffffffu, partial, 2);
                if ((lane & 3) == 0 && (e0 + rowl) < N_EDGES)
                    atomicAdd(&g_m[sTgt[rowl] * 32 + i_out], partial);
            }
        }
    }
}

// ---------------- GRU cell (f32x2 k-pairs); writes fp16 mirror; re-zeros m ----
__global__ void __launch_bounds__(256) k_gru(const float* __restrict__ Wih,
                                             const float* __restrict__ Whh,
                                             const float* __restrict__ bih,
                                             const float* __restrict__ bhh) {
    __shared__ ull sWi2[3 * 16 * 32];
    __shared__ ull sWh2[3 * 16 * 32];
    __shared__ float sbi[96];
    __shared__ float sbh[96];
    int t = threadIdx.x;
    for (int i = t; i < 1536; i += 256) {
        int g  = i >> 9;
        int k2 = (i >> 5) & 15;
        int c  = i & 31;
        int k  = g * 32 + 2 * k2;
        sWi2[i] = pkab(Wih[k * 32 + c], Wih[(k + 1) * 32 + c]);
        sWh2[i] = pkab(Whh[k * 32 + c], Whh[(k + 1) * 32 + c]);
    }
    if (t < 96) { sbi[t] = bih[t]; sbh[t] = bhh[t]; }
    __syncthreads();
    int n = blockIdx.x * blockDim.x + t;
    if (n >= N_NODES) return;

    float mv[32], hv[32];
    const float4* mp = (const float4*)&g_m[n * 32];
    const float4* hp = (const float4*)&g_h[n * 32];
    #pragma unroll
    for (int q = 0; q < 8; q++) {
        float4 a = mp[q]; mv[q*4]=a.x; mv[q*4+1]=a.y; mv[q*4+2]=a.z; mv[q*4+3]=a.w;
        float4 b = hp[q]; hv[q*4]=b.x; hv[q*4+1]=b.y; hv[q*4+2]=b.z; hv[q*4+3]=b.w;
    }
    float4* mz = (float4*)&g_m[n * 32];
    #pragma unroll
    for (int q = 0; q < 8; q++) mz[q] = make_float4(0.f, 0.f, 0.f, 0.f);

    #pragma unroll 1
    for (int k2 = 0; k2 < 16; k2++) {
        int k = 2 * k2;
        ull accr = pkab(sbi[k] + sbh[k], sbi[k + 1] + sbh[k + 1]);
        ull accz = pkab(sbi[32 + k] + sbh[32 + k], sbi[33 + k] + sbh[33 + k]);
        ull accn = pkab(sbi[64 + k], sbi[65 + k]);
        ull acch = pkab(sbh[64 + k], sbh[65 + k]);
        const ull* wir = &sWi2[(0 * 16 + k2) * 32];
        const ull* wiz = &sWi2[(1 * 16 + k2) * 32];
        const ull* win = &sWi2[(2 * 16 + k2) * 32];
        const ull* whr = &sWh2[(0 * 16 + k2) * 32];
        const ull* whz = &sWh2[(1 * 16 + k2) * 32];
        const ull* whn = &sWh2[(2 * 16 + k2) * 32];
        #pragma unroll
        for (int c = 0; c < 32; c++) {
            ull pm = pk2(mv[c]);
            ull ph = pk2(hv[c]);
            accr = fma2(pm, wir[c], accr);
            accr = fma2(ph, whr[c], accr);
            accz = fma2(pm, wiz[c], accz);
            accz = fma2(ph, whz[c], accz);
            accn = fma2(pm, win[c], accn);
            acch = fma2(ph, whn[c], acch);
        }
        float rlo, rhi, zlo, zhi, nlo, nhi, hlo, hhi;
        unpk2(accr, rlo, rhi);
        unpk2(accz, zlo, zhi);
        unpk2(accn, nlo, nhi);
        unpk2(acch, hlo, hhi);
        float r0 = sigm(rlo), z0 = sigm(zlo);
        float n0 = tanhf(nlo + r0 * hlo);
        float r1 = sigm(rhi), z1 = sigm(zhi);
        float n1 = tanhf(nhi + r1 * hhi);
        float2 hnew;
        hnew.x = (1.0f - z0) * n0 + z0 * hv[k];
        hnew.y = (1.0f - z1) * n1 + z1 * hv[k + 1];
        *(float2*)&g_h[n * 32 + k] = hnew;
        *(__half2*)&g_hh[n * 32 + k] = __floats2half2_rn(hnew.x, hnew.y);
    }
}

// ---------------- graph segment offsets (batch_indices sorted) ----------------
__global__ void k_offs(const int* __restrict__ batch) {
    int n = blockIdx.x * blockDim.x + threadIdx.x;
    if (n >= N_NODES) return;
    int b = batch[n];
    int prev = (n == 0) ? -1 : batch[n - 1];
    for (int g = prev + 1; g <= b; g++) g_offs[g] = n;
    if (n == N_NODES - 1)
        for (int g = b + 1; g <= NG; g++) g_offs[g] = N_NODES;
}

// ---------------- Set2Set attention + readout (online softmax, warp/graph) ----
__global__ void __launch_bounds__(256) k_attend() {
    int lane = threadIdx.x & 31;
    int g = (blockIdx.x * blockDim.x + threadIdx.x) >> 5;
    if (g >= NG) return;
    int s = g_offs[g], tEnd = g_offs[g + 1];
    float q = g_sh[g * 32 + lane];
    float maxv = -CUDART_INF_F, denom = 0.0f, racc = 0.0f;

    for (int base = s; base < tEnd; base += 32) {
        int n = base + lane;
        bool act = n < tEnd;
        int nn = act ? n : s;
        float rv[32];
        const float4* hp4 = (const float4*)&g_h[nn * 32];
        #pragma unroll
        for (int q4 = 0; q4 < 8; q4++) {
            float4 v = hp4[q4];
            rv[q4*4] = v.x; rv[q4*4+1] = v.y; rv[q4*4+2] = v.z; rv[q4*4+3] = v.w;
        }
        float ev = 0.0f;
        #pragma unroll
        for (int j = 0; j < 32; j++)
            ev += rv[j] * __shfl_sync(0xffffffffu, q, j);
        float e_n = act ? ev : -CUDART_INF_F;
        float cm = warpMax(e_n);
        float nm = fmaxf(maxv, cm);
        float scale = (maxv == -CUDART_INF_F) ? 0.0f : expf(maxv - nm);
        float p = act ? expf(e_n - nm) : 0.0f;
        float ps = warpSum(p);
        denom = denom * scale + ps;
        racc *= scale;
        maxv = nm;
        int cnt = min(32, tEnd - base);
        for (int n2 = 0; n2 < cnt; n2++) {
            float pn = __shfl_sync(0xffffffffu, p, n2);
            racc += pn * g_h[(base + n2) * 32 + lane];
        }
    }
    g_rr[g * 32 + lane] = (denom > 0.0f) ? (racc / denom) : 0.0f;
}

// ---------------- Set2Set LSTM step (fused mini-GEMM, 64 graphs/block) --------
__global__ void __launch_bounds__(256) k_lstm(const float* __restrict__ Wih,
                                              const float* __restrict__ Whh,
                                              const float* __restrict__ bih,
                                              const float* __restrict__ bhh) {
    __shared__ float sx[64 * 64];
    __shared__ float sW[48 * 128];
    int t  = threadIdx.x;
    int g0 = blockIdx.x * 64;
    int k  = t & 31;
    int rg = t >> 5;

    for (int i = t; i < 64 * 64; i += 256) {
        int g = i >> 6, c = i & 63;
        int gg = g0 + g;
        float v = 0.0f;
        if (gg < NG) v = (c < 32) ? g_sh[gg * 32 + c] : g_rr[gg * 32 + (c - 32)];
        sx[i] = v;
    }

    float acc[8][4];
    #pragma unroll
    for (int r = 0; r < 8; r++)
        #pragma unroll
        for (int j = 0; j < 4; j++) acc[r][j] = 0.0f;

    #pragma unroll 1
    for (int kc = 0; kc < 2; kc++) {
        __syncthreads();
        for (int i = t; i < 48 * 128; i += 256) {
            int c  = kc * 48 + (i >> 7);
            int kk = i & 127;
            sW[i] = (c < 64) ? Wih[kk * 64 + c] : Whh[kk * 32 + (c - 64)];
        }
        __syncthreads();
        for (int cc = 0; cc < 48; cc++) {
            int c  = kc * 48 + cc;
            int cx = (c < 64) ? c : (c - 64);
            float b0 = sW[cc * 128 + k];
            float b1 = sW[cc * 128 + 32 + k];
            float b2v = sW[cc * 128 + 64 + k];
            float b3 = sW[cc * 128 + 96 + k];
            #pragma unroll
            for (int r = 0; r < 8; r++) {
                float a = sx[(rg * 8 + r) * 64 + cx];
                acc[r][0] += a * b0;
                acc[r][1] += a * b1;
                acc[r][2] += a * b2v;
                acc[r][3] += a * b3;
            }
        }
    }

    float bi0 = __ldg(&bih[k])      + __ldg(&bhh[k]);
    float bf  = __ldg(&bih[32 + k]) + __ldg(&bhh[32 + k]);
    float bg  = __ldg(&bih[64 + k]) + __ldg(&bhh[64 + k]);
    float bo  = __ldg(&bih[96 + k]) + __ldg(&bhh[96 + k]);
    #pragma unroll
    for (int r = 0; r < 8; r++) {
        int gg = g0 + rg * 8 + r;
        if (gg >= NG) break;
        float i_ = sigm(acc[r][0] + bi0);
        float f_ = sigm(acc[r][1] + bf);
        float gv = tanhf(acc[r][2] + bg);
        float o_ = sigm(acc[r][3] + bo);
        float cn = f_ * g_sc[gg * 32 + k] + i_ * gv;
        g_sc[gg * 32 + k] = cn;
        g_sh[gg * 32 + k] = o_ * tanhf(cn);
    }
}

// ---------------- output head ----------------
__global__ void k_output(const float* __restrict__ W1, const float* __restrict__ b1,
                         const float* __restrict__ W2, const float* __restrict__ b2,
                         float* __restrict__ out) {
    int g = blockIdx.x * blockDim.x + threadIdx.x;
    if (g >= NG) return;
    float emb[64];
    #pragma unroll
    for (int c = 0; c < 32; c++) {
        emb[c]      = g_sh[g * 32 + c];
        emb[32 + c] = g_rr[g * 32 + c];
    }
    float hid[32];
    #pragma unroll
    for (int c = 0; c < 32; c++) {
        float acc = __ldg(&b1[c]);
        #pragma unroll
        for (int d = 0; d < 64; d++) acc += emb[d] * __ldg(&W1[d * 32 + c]);
        hid[c] = fmaxf(acc, 0.0f);
    }
    #pragma unroll
    for (int kk = 0; kk < 3; kk++) {
        float acc = __ldg(&b2[kk]);
        #pragma unroll
        for (int c = 0; c < 32; c++) acc += hid[c] * __ldg(&W2[c * 3 + kk]);
        out[g * 3 + kk] = acc;
    }
}

// ---------------- launch ----------------
extern "C" void kernel_launch(void* const* d_in, const int* in_sizes, int n_in,
                              void* d_out, int out_size) {
    const float* nf     = (const float*)d_in[0];
    const float* ef     = (const float*)d_in[1];
    const float* enc_W  = (const float*)d_in[2];
    const float* enc_b  = (const float*)d_in[3];
    const float* e_W1   = (const float*)d_in[4];
    const float* e_b1   = (const float*)d_in[5];
    const float* e_W2   = (const float*)d_in[6];
    const float* e_b2   = (const float*)d_in[7];
    const float* gWih   = (const float*)d_in[8];
    const float* gWhh   = (const float*)d_in[9];
    const float* gbih   = (const float*)d_in[10];
    const float* gbhh   = (const float*)d_in[11];
    const float* lWih   = (const float*)d_in[12];
    const float* lWhh   = (const float*)d_in[13];
    const float* lbih   = (const float*)d_in[14];
    const float* lbhh   = (const float*)d_in[15];
    const float* oW1    = (const float*)d_in[16];
    const float* ob1    = (const float*)d_in[17];
    const float* oW2    = (const float*)d_in[18];
    const float* ob2    = (const float*)d_in[19];
    const int*   eidx   = (const int*)d_in[20];
    const int*   batch  = (const int*)d_in[21];
    float* out = (float*)d_out;

    // order chosen so the 4th launch (ncu capture target) is k_msg_fused
    k_packW2<<<(64 * 1024 + 255) / 256, 256>>>(e_W2);
    k_encode<<<(N_NODES + 255) / 256, 256>>>(nf, enc_W, enc_b);
    k_edgehid<<<(N_EDGES + 255) / 256, 256>>>(ef, e_W1, e_b1);

    for (int r = 0; r < 3; r++) {
        k_msg_fused<<<(N_EDGES + 127) / 128, 256>>>(eidx, e_b2);
        k_gru<<<(N_NODES + 255) / 256, 256>>>(gWih, gWhh, gbih, gbhh);
    }

    k_zero_s2s<<<(NG * H + 255) / 256, 256>>>();
    k_offs<<<(N_NODES + 255) / 256, 256>>>(batch);

    for (int s = 0; s < 4; s++) {
        k_attend<<<(NG * 32 + 255) / 256, 256>>>();
        k_lstm<<<(NG + 63) / 64, 256>>>(lWih, lWhh, lbih, lbhh);
    }

    k_output<<<(NG + 255) / 256, 256>>>(oW1, ob1, oW2, ob2, out);
}